// round 1
// baseline (speedup 1.0000x reference)
#include <cuda_runtime.h>
#include <cuda_bf16.h>
#include <math.h>

// Problem constants
#define Bn   32
#define Sn   512
#define Hn   512
#define WDn  512
#define Nn   (Bn * Sn)        // 16384 tokens
#define NGn  8
#define KCAT 2048             // [h | hb | ha | sw_h]
#define NUM_LAYERS 4

static const long GS = (long)Nn * Hn;  // 8,388,608 elems per gate-plane

// ---------------- scratch (device globals; no allocations allowed) ----------------
__device__ float g_embproj[(long)NGn * Nn * Hn];   // 256 MB : emb @ Wi  (layer-invariant)
__device__ float g_Z[(long)NGn * Nn * Hn];         // 256 MB : gate pre-activations
__device__ float g_Xcat[(long)Nn * KCAT];          // 128 MB : [h | hb | ha | sw_h]
__device__ float g_Wcat[(long)NGn * KCAT * Hn];    //  32 MB : [Wx ; Wh ; Ws]
__device__ float g_hA[(long)Nn * Hn];              //  32 MB
__device__ float g_hB[(long)Nn * Hn];
__device__ float g_cA[(long)Nn * Hn];
__device__ float g_cB[(long)Nn * Hn];
__device__ float g_gfz[(long)Nn * Hn];             //  32 MB : h @ gWhf
__device__ float g_dh[2][Bn * Hn];
__device__ float g_dc[2][Bn * Hn];
__device__ float g_comb[Bn * Hn];
__device__ float g_gd[Bn * Hn];
__device__ float g_go[Bn * Hn];
__device__ float g_dgf[Bn * Hn];
__device__ float g_biasrow[NGn * Bn * Hn];         // td_h @ Wd[g] + b[g]

__device__ __forceinline__ float sigf(float x) { return 1.0f / (1.0f + expf(-x)); }

// ---------------- generic tiled fp32 GEMM: C[g] = A @ B[g] (+ add[g]) (+ rowbias[g]) ----
// BM=BN=128, BK=8, 256 threads, 8x8 micro-tile. N and M divisible by 128, K by 8.
__global__ __launch_bounds__(256)
void sgemm128(const float* __restrict__ A, const float* __restrict__ Bm,
              float* __restrict__ C, int M, int N, int K, int lda,
              long Bstride, long Cstride,
              const float* __restrict__ addmat, long addstride,
              const float* __restrict__ rowbias, long biasstride)
{
    const int g = blockIdx.z;
    const float* Bg   = Bm + (long)g * Bstride;
    float*       Cg   = C  + (long)g * Cstride;
    const float* addg = addmat  ? addmat  + (long)g * addstride  : nullptr;
    const float* bg   = rowbias ? rowbias + (long)g * biasstride : nullptr;

    __shared__ float As[8][128];
    __shared__ float Bs[8][128];

    const int tid = threadIdx.x;
    const int tx = tid & 15, ty = tid >> 4;
    const int rowBase = blockIdx.y * 128;
    const int colBase = blockIdx.x * 128;

    const int aRow = tid >> 1;
    const int aVec = (tid & 1) << 2;
    const int bRow = tid >> 5;
    const int bCol = (tid & 31) << 2;

    float acc[8][8];
    #pragma unroll
    for (int i = 0; i < 8; i++)
        #pragma unroll
        for (int j = 0; j < 8; j++) acc[i][j] = 0.0f;

    for (int k0 = 0; k0 < K; k0 += 8) {
        float4 av = *reinterpret_cast<const float4*>(A  + (long)(rowBase + aRow) * lda + k0 + aVec);
        float4 bv = *reinterpret_cast<const float4*>(Bg + (long)(k0 + bRow) * N + colBase + bCol);
        __syncthreads();
        As[aVec + 0][aRow] = av.x;
        As[aVec + 1][aRow] = av.y;
        As[aVec + 2][aRow] = av.z;
        As[aVec + 3][aRow] = av.w;
        *reinterpret_cast<float4*>(&Bs[bRow][bCol]) = bv;
        __syncthreads();
        #pragma unroll
        for (int kk = 0; kk < 8; kk++) {
            float a[8], b[8];
            float4 a0 = *reinterpret_cast<const float4*>(&As[kk][ty * 8]);
            float4 a1 = *reinterpret_cast<const float4*>(&As[kk][ty * 8 + 4]);
            float4 b0 = *reinterpret_cast<const float4*>(&Bs[kk][tx * 8]);
            float4 b1 = *reinterpret_cast<const float4*>(&Bs[kk][tx * 8 + 4]);
            a[0]=a0.x; a[1]=a0.y; a[2]=a0.z; a[3]=a0.w; a[4]=a1.x; a[5]=a1.y; a[6]=a1.z; a[7]=a1.w;
            b[0]=b0.x; b[1]=b0.y; b[2]=b0.z; b[3]=b0.w; b[4]=b1.x; b[5]=b1.y; b[6]=b1.z; b[7]=b1.w;
            #pragma unroll
            for (int i = 0; i < 8; i++)
                #pragma unroll
                for (int j = 0; j < 8; j++)
                    acc[i][j] = fmaf(a[i], b[j], acc[i][j]);
        }
    }

    #pragma unroll
    for (int i = 0; i < 8; i++) {
        int r = rowBase + ty * 8 + i;
        long off = (long)r * N + colBase + tx * 8;
        int bb = r >> 9;  // batch index (S = 512)
        #pragma unroll
        for (int j = 0; j < 8; j++) {
            float v = acc[i][j];
            if (addg) v += addg[off + j];
            if (bg)   v += bg[(long)bb * N + colBase + tx * 8 + j];
            Cg[off + j] = v;
        }
    }
}

// ---------------- column mean over sequence: out[b,k] = mean_s in[b,s,k] -----------
__global__ void colmean_kernel(const float* __restrict__ in, float* __restrict__ out)
{
    int id = blockIdx.x * blockDim.x + threadIdx.x;   // 16384 = B*H
    if (id >= Bn * Hn) return;
    int b = id >> 9, k = id & 511;
    const float* p = in + (long)b * Sn * Hn + k;
    float s = 0.0f;
    #pragma unroll 8
    for (int t = 0; t < Sn; t++) s += p[(long)t * Hn];
    out[id] = s * (1.0f / (float)Sn);
}

// ---------------- small matmuls on dummy_h/combined (B=32 rows) --------------------
// task 0: gd  = sig(dh@gW0 + comb@gW1 + gb0)
// task 1: go  = sig(dh@gW2 + comb@gW3 + gb1)
// task 2: dgf =     dh@gW4 + gb2                      (gf bias per batch)
// task 3..10: biasrow[g] = dh@Wd[g] + b[g]
__global__ __launch_bounds__(512)
void smallmm_kernel(const float* __restrict__ dh, const float* __restrict__ comb,
                    const float* __restrict__ gW, const float* __restrict__ gb,
                    const float* __restrict__ Wd, const float* __restrict__ bvec,
                    float* __restrict__ gd, float* __restrict__ go,
                    float* __restrict__ dgf, float* __restrict__ biasrow)
{
    const int task = blockIdx.x;   // 0..10
    const int b = blockIdx.y;      // 0..31
    const int k = threadIdx.x;     // 0..511
    __shared__ float xs[512];
    __shared__ float ys[512];
    xs[k] = dh[b * Hn + k];
    if (task < 2) ys[k] = comb[b * Hn + k];
    __syncthreads();

    const int MM = Hn * Hn;        // 262144
    if (task == 0) {
        const float* W1 = gW;           const float* W2 = gW + MM;
        float acc = gb[k];
        #pragma unroll 8
        for (int i = 0; i < Hn; i++)
            acc += xs[i] * W1[i * Hn + k] + ys[i] * W2[i * Hn + k];
        gd[b * Hn + k] = sigf(acc);
    } else if (task == 1) {
        const float* W1 = gW + 2 * MM;  const float* W2 = gW + 3 * MM;
        float acc = gb[Hn + k];
        #pragma unroll 8
        for (int i = 0; i < Hn; i++)
            acc += xs[i] * W1[i * Hn + k] + ys[i] * W2[i * Hn + k];
        go[b * Hn + k] = sigf(acc);
    } else if (task == 2) {
        const float* W1 = gW + 4 * MM;
        float acc = gb[2 * Hn + k];
        #pragma unroll 8
        for (int i = 0; i < Hn; i++) acc += xs[i] * W1[i * Hn + k];
        dgf[b * Hn + k] = acc;
    } else {
        int g = task - 3;
        const float* W1 = Wd + (long)g * MM;
        float acc = bvec[g * Hn + k];
        #pragma unroll 8
        for (int i = 0; i < Hn; i++) acc += xs[i] * W1[i * Hn + k];
        biasrow[(g * Bn + b) * Hn + k] = acc;
    }
}

// ---------------- scores softmax over S+1 and dummy state update -------------------
__global__ void scorereduce_kernel(const float* __restrict__ gfz, const float* __restrict__ dgf,
                                   const float* __restrict__ gd, const float* __restrict__ go,
                                   const float* __restrict__ c, const float* __restrict__ dcold,
                                   float* __restrict__ dcnew, float* __restrict__ dhnew)
{
    int id = blockIdx.x * blockDim.x + threadIdx.x;   // B*H
    if (id >= Bn * Hn) return;
    int b = id >> 9, k = id & 511;
    float add = dgf[id];
    float num = 0.0f, den = 0.0f;
    long base = ((long)b * Sn) * Hn + k;
    for (int s = 0; s < Sn; s++) {
        long idx = base + (long)s * Hn;
        float gv = sigf(gfz[idx] + add);      // values in (0,1): exp is safe
        float e = expf(gv);
        num += e * c[idx];
        den += e;
    }
    float eg = expf(gd[id]);
    num += eg * dcold[id];
    den += eg;
    float dcn = num / den;
    dcnew[id] = dcn;
    dhnew[id] = go[id] * tanhf(dcn);
}

// ---------------- build Xcat = [h | h(t-1)+h(t-2) | h(t+1)+h(t+2) | sw_h] ----------
__global__ void buildxcat_kernel(const float* __restrict__ h, const int* __restrict__ pos,
                                 float* __restrict__ X)
{
    long id = (long)blockIdx.x * blockDim.x + threadIdx.x;   // N*H
    if (id >= (long)Nn * Hn) return;
    int n = (int)(id >> 9), k = (int)(id & 511);
    int b = n >> 9, s = n & 511;
    long hb_base = (long)n * Hn + k;
    float hv = h[hb_base];
    float hb = (s >= 1 ? h[hb_base - Hn] : 0.0f) + (s >= 2 ? h[hb_base - 2 * Hn] : 0.0f);
    float ha = (s <= Sn - 2 ? h[hb_base + Hn] : 0.0f) + (s <= Sn - 3 ? h[hb_base + 2 * Hn] : 0.0f);
    int p = pos[n];
    float sw = (p > 0) ? h[((long)((b << 9) + p - 1)) * Hn + k] : 0.0f;
    long xo = (long)n * KCAT + k;
    X[xo]            = hv;
    X[xo + 512]      = hb;
    X[xo + 1024]     = ha;
    X[xo + 1536]     = sw;
}

// ---------------- build Wcat = [Wx ; Wh ; Ws] per gate -----------------------------
__global__ void buildwcat_kernel(const float* __restrict__ Wx, const float* __restrict__ Wh,
                                 const float* __restrict__ Ws, float* __restrict__ W)
{
    long id = (long)blockIdx.x * blockDim.x + threadIdx.x;   // NG*KCAT*H
    if (id >= (long)NGn * KCAT * Hn) return;
    int k = (int)(id & 511);
    long rg = id >> 9;
    int r = (int)(rg % KCAT);
    int g = (int)(rg / KCAT);
    float v;
    if (r < 512)        v = Wx[((long)g * 512  + r)        * Hn + k];
    else if (r < 1536)  v = Wh[((long)g * 1024 + (r - 512)) * Hn + k];
    else                v = Ws[((long)g * 512  + (r - 1536)) * Hn + k];
    W[id] = v;
}

// ---------------- gate combine: softmax over 6 sigmoids + cell/hidden update -------
__global__ void combine_kernel(const float* __restrict__ Z, const float* __restrict__ c_in,
                               const int* __restrict__ pos, const float* __restrict__ dcold,
                               float* __restrict__ h_out, float* __restrict__ c_out)
{
    long id = (long)blockIdx.x * blockDim.x + threadIdx.x;   // N*H
    if (id >= (long)Nn * Hn) return;
    int n = (int)(id >> 9), k = (int)(id & 511);
    int b = n >> 9, s = n & 511;
    const long gs = (long)Nn * Hn;

    float z[8];
    #pragma unroll
    for (int g = 0; g < 8; g++) z[g] = Z[(long)g * gs + id];

    float es[6], sum = 0.0f;
    #pragma unroll
    for (int i = 0; i < 6; i++) { es[i] = expf(sigf(z[i])); sum += es[i]; }
    float inv = 1.0f / sum;

    long cb_base = (long)n * Hn + k;
    float cb = (s >= 1 ? c_in[cb_base - Hn] : 0.0f) + (s >= 2 ? c_in[cb_base - 2 * Hn] : 0.0f);
    float ca = (s <= Sn - 2 ? c_in[cb_base + Hn] : 0.0f) + (s <= Sn - 3 ? c_in[cb_base + 2 * Hn] : 0.0f);
    int p = pos[n];
    float swc = (p > 0) ? c_in[((long)((b << 9) + p - 1)) * Hn + k] : 0.0f;
    float cf  = c_in[cb_base];
    float tdc = dcold[(b << 9) + k];

    float u = tanhf(z[7]);
    float o = sigf(z[6]);
    float cn = (es[0] * cb + es[1] * ca + es[2] * cf + es[3] * tdc + es[4] * swc + es[5] * u) * inv;
    c_out[id] = cn;
    h_out[id] = o * tanhf(cn);
}

// =====================================================================================
extern "C" void kernel_launch(void* const* d_in, const int* in_sizes, int n_in,
                              void* d_out, int out_size)
{
    const float* word_inputs = (const float*)d_in[0];
    const float* init_h      = (const float*)d_in[1];
    const float* init_c      = (const float*)d_in[2];
    const float* Wx          = (const float*)d_in[3];
    const float* Wh          = (const float*)d_in[4];
    const float* Wi          = (const float*)d_in[5];
    const float* Wd          = (const float*)d_in[6];
    const float* Ws          = (const float*)d_in[7];
    const float* bvec        = (const float*)d_in[8];
    const float* gW          = (const float*)d_in[9];
    const float* gb          = (const float*)d_in[10];
    const int*   postab      = (const int*)d_in[11];
    // d_in[12] = mask (all ones, unused), d_in[13] = num_layers (fixed 4)
    float* out = (float*)d_out;

    float *embproj, *Zb, *Xcat, *Wcat, *hA, *hB, *cA, *cB, *gfz;
    float *dh, *dc, *comb, *gd, *go, *dgf, *biasrow;
    cudaGetSymbolAddress((void**)&embproj, g_embproj);
    cudaGetSymbolAddress((void**)&Zb,      g_Z);
    cudaGetSymbolAddress((void**)&Xcat,    g_Xcat);
    cudaGetSymbolAddress((void**)&Wcat,    g_Wcat);
    cudaGetSymbolAddress((void**)&hA,      g_hA);
    cudaGetSymbolAddress((void**)&hB,      g_hB);
    cudaGetSymbolAddress((void**)&cA,      g_cA);
    cudaGetSymbolAddress((void**)&cB,      g_cB);
    cudaGetSymbolAddress((void**)&gfz,     g_gfz);
    cudaGetSymbolAddress((void**)&dh,      g_dh);
    cudaGetSymbolAddress((void**)&dc,      g_dc);
    cudaGetSymbolAddress((void**)&comb,    g_comb);
    cudaGetSymbolAddress((void**)&gd,      g_gd);
    cudaGetSymbolAddress((void**)&go,      g_go);
    cudaGetSymbolAddress((void**)&dgf,     g_dgf);
    cudaGetSymbolAddress((void**)&biasrow, g_biasrow);

    const long stateBytes = (long)Nn * Hn * sizeof(float);
    const int  MM = Hn * Hn;

    // ---- init ----
    cudaMemcpyAsync(hA, init_h, stateBytes, cudaMemcpyDeviceToDevice);
    cudaMemcpyAsync(cA, init_c, stateBytes, cudaMemcpyDeviceToDevice);
    colmean_kernel<<<64, 256>>>(init_h, dh + 0);            // dh[0]
    colmean_kernel<<<64, 256>>>(init_c, dc + 0);            // dc[0]
    buildwcat_kernel<<<(int)(((long)NGn * KCAT * Hn) / 256), 256>>>(Wx, Wh, Ws, Wcat);
    // emb_proj[g] = word_inputs @ Wi[g]  (once; reused by all layers)
    sgemm128<<<dim3(Hn / 128, Nn / 128, NGn), 256>>>(
        word_inputs, Wi, embproj, Nn, Hn, WDn, WDn,
        (long)MM, GS, nullptr, 0, nullptr, 0);

    for (int L = 0; L < NUM_LAYERS; L++) {
        const float* h_in = (L & 1) ? hB : hA;
        const float* c_in = (L & 1) ? cB : cA;
        float* h_out = (L == NUM_LAYERS - 1) ? out : ((L & 1) ? hA : hB);
        float* c_out = (L & 1) ? cA : cB;
        float* dh_in  = dh + (L & 1) * (Bn * Hn);
        float* dh_out = dh + (1 - (L & 1)) * (Bn * Hn);
        float* dc_in  = dc + (L & 1) * (Bn * Hn);
        float* dc_out = dc + (1 - (L & 1)) * (Bn * Hn);

        // combined = mean_s h
        colmean_kernel<<<64, 256>>>(h_in, comb);
        // gd, go, dgf, biasrow (all B=32-row matmuls)
        smallmm_kernel<<<dim3(11, Bn), 512>>>(dh_in, comb, gW, gb, Wd, bvec,
                                              gd, go, dgf, biasrow);
        // gfz = h @ gWhf
        sgemm128<<<dim3(Hn / 128, Nn / 128, 1), 256>>>(
            h_in, gW + 5 * MM, gfz, Nn, Hn, Hn, Hn,
            0, 0, nullptr, 0, nullptr, 0);
        // dummy state update via softmax over S+1 scores
        scorereduce_kernel<<<64, 256>>>(gfz, dgf, gd, go, c_in, dc_in, dc_out, dh_out);
        // Xcat = [h | hb | ha | sw_h]
        buildxcat_kernel<<<(int)(((long)Nn * Hn) / 256), 256>>>(h_in, postab, Xcat);
        // Z[g] = Xcat @ Wcat[g] + emb_proj[g] + biasrow[g]
        sgemm128<<<dim3(Hn / 128, Nn / 128, NGn), 256>>>(
            Xcat, Wcat, Zb, Nn, Hn, KCAT, KCAT,
            (long)KCAT * Hn, GS, embproj, GS, biasrow, (long)Bn * Hn);
        // gates + cell/hidden update
        combine_kernel<<<(int)(((long)Nn * Hn) / 256), 256>>>(Zb, c_in, postab, dc_in,
                                                              h_out, c_out);
    }
}

// round 3
// speedup vs baseline: 3.1654x; 3.1654x over previous
#include <cuda_runtime.h>
#include <cuda_bf16.h>
#include <math.h>
#include <stdint.h>

// Problem constants
#define Bn   32
#define Sn   512
#define Hn   512
#define WDn  512
#define Nn   (Bn * Sn)        // 16384 tokens
#define NGn  8
#define KBIG 2560             // [h | hb | ha | sw_h | emb]
#define NTOT 4096             // 8 gates * 512
#define NUM_LAYERS 4

static const long GS = (long)Nn * Hn;  // 8,388,608 elems per gate-plane

// ---------------- scratch (device globals; no allocations allowed) ----------------
__device__ float g_Z[(long)NGn * Nn * Hn];         // 256 MB : gate pre-activations
__device__ float g_Xbig[(long)Nn * KBIG];          // 160 MB : [h | hb | ha | sw_h | emb]
__device__ float g_Wbig[(long)NTOT * KBIG];        //  40 MB : K-major weights, row = out col
__device__ float g_gWT[(long)Hn * Hn];             //   1 MB : gWhf transposed (K-major)
__device__ float g_hA[(long)Nn * Hn];
__device__ float g_hB[(long)Nn * Hn];
__device__ float g_cA[(long)Nn * Hn];
__device__ float g_cB[(long)Nn * Hn];
__device__ float g_gfz[(long)Nn * Hn];
__device__ float g_dh[2][Bn * Hn];
__device__ float g_dc[2][Bn * Hn];
__device__ float g_comb[Bn * Hn];
__device__ float g_gd[Bn * Hn];
__device__ float g_go[Bn * Hn];
__device__ float g_dgf[Bn * Hn];
__device__ float g_biasrow[NGn * Bn * Hn];         // td_h @ Wd[g] + b[g]

__device__ __forceinline__ float sigf(float x) { return 1.0f / (1.0f + expf(-x)); }
__device__ __forceinline__ float tf32r(float x) {
    uint32_t u; asm("cvt.rna.tf32.f32 %0, %1;" : "=r"(u) : "f"(x));
    return __uint_as_float(u);
}

// ======================= PTX helpers =====================================
__device__ __forceinline__ uint32_t smem_u32(const void* p) {
    uint32_t a;
    asm("{ .reg .u64 t; cvta.to.shared.u64 t, %1; cvt.u32.u64 %0, t; }" : "=r"(a) : "l"(p));
    return a;
}
#define CP_ASYNC16(dst, src) \
    asm volatile("cp.async.cg.shared.global [%0], [%1], 16;" \
        :: "r"(dst), "l"(__cvta_generic_to_global(src)))
#define CP_COMMIT()   asm volatile("cp.async.commit_group;" ::: "memory")
#define CP_WAIT(N)    asm volatile("cp.async.wait_group %0;" :: "n"(N) : "memory")

// m16n8k8 tf32 mma, row.col, f32 accum
#define MMA_TF32(d, a, b) \
    asm volatile("mma.sync.aligned.m16n8k8.row.col.f32.tf32.tf32.f32 " \
        "{%0,%1,%2,%3},{%4,%5,%6,%7},{%8,%9},{%0,%1,%2,%3};" \
        : "+f"((d)[0]), "+f"((d)[1]), "+f"((d)[2]), "+f"((d)[3]) \
        : "r"(__float_as_uint((a)[0])), "r"(__float_as_uint((a)[1])), \
          "r"(__float_as_uint((a)[2])), "r"(__float_as_uint((a)[3])), \
          "r"(__float_as_uint((b)[0])), "r"(__float_as_uint((b)[1])))

// smem tile: row-major [128 rows][32 k floats], XOR-swizzled 16B chunks.
// byte offset of element (row m, k index kk):
#define SMOFF(m, kk) ((m) * 128 + ((((kk) >> 2) ^ ((m) & 7)) << 4) + (((kk) & 3) << 2))

// ======================= mma.sync tf32 tensor-core GEMM ============================
// D[m, col] = sum_k A[m,k] * Bw[gate*512 + col, k]
// A: M x Kel row-major (lda = Kel elems). Bw: K-major rows (one row per out col).
// out: outp + gate*gateStride + m*512 + col.   biasrow: per (gate, batch) 512-row.
#define STAGES 3
#define GEMM_SMEM (STAGES * 32768)

__global__ __launch_bounds__(256, 2)
void mmagemm(const float* __restrict__ A, int lda,
             const float* __restrict__ Bw, int Kel,
             float* __restrict__ outp, long gateStride,
             const float* __restrict__ biasrow)
{
    extern __shared__ char sm[];
    const int tid = threadIdx.x, wid = tid >> 5, lane = tid & 31;
    const int gq = lane >> 2, t4 = lane & 3;
    const int rowBase = blockIdx.y * 128;
    const int colBase = blockIdx.x * 128;          // within 512
    const int gate = blockIdx.z;
    const float* Aorig = A  + (long)rowBase * lda;
    const float* Borig = Bw + ((long)gate * 512 + colBase) * Kel;
    const int T = Kel >> 5;                        // K chunks of 32
    const int wm = (wid & 1) * 64, wn = (wid >> 1) * 32;

    float c[4][4][4];
    #pragma unroll
    for (int i = 0; i < 4; i++)
        #pragma unroll
        for (int j = 0; j < 4; j++)
            #pragma unroll
            for (int q = 0; q < 4; q++) c[i][j][q] = 0.0f;

    auto issue = [&](int t) {
        const int s = t % STAGES;
        const uint32_t sA = smem_u32(sm) + s * 32768;
        const uint32_t sB = sA + 16384;
        const long k0 = (long)t * 32;
        #pragma unroll
        for (int i = 0; i < 4; i++) {              // A: 1024 chunks of 16B
            int chunk = i * 256 + tid;
            int m = chunk >> 3, ch = chunk & 7;
            CP_ASYNC16(sA + m * 128 + ((ch ^ (m & 7)) << 4),
                       Aorig + (long)m * lda + k0 + ch * 4);
        }
        #pragma unroll
        for (int i = 0; i < 4; i++) {              // B: 1024 chunks of 16B
            int chunk = i * 256 + tid;
            int n = chunk >> 3, ch = chunk & 7;
            CP_ASYNC16(sB + n * 128 + ((ch ^ (n & 7)) << 4),
                       Borig + (long)n * Kel + k0 + ch * 4);
        }
    };

    issue(0); CP_COMMIT();
    issue(1); CP_COMMIT();

    for (int t = 0; t < T; t++) {
        CP_WAIT(1);
        __syncthreads();
        const int s = t % STAGES;
        const char* tA = sm + s * 32768;
        const char* tB = tA + 16384;
        #pragma unroll
        for (int ks = 0; ks < 4; ks++) {
            const int k8 = ks * 8;
            const int kk0 = k8 + t4, kk1 = k8 + t4 + 4;
            float a[4][4], b[4][2];
            #pragma unroll
            for (int mi = 0; mi < 4; mi++) {
                int m = wm + mi * 16 + gq;
                a[mi][0] = *(const float*)(tA + SMOFF(m,     kk0));
                a[mi][1] = *(const float*)(tA + SMOFF(m + 8, kk0));
                a[mi][2] = *(const float*)(tA + SMOFF(m,     kk1));
                a[mi][3] = *(const float*)(tA + SMOFF(m + 8, kk1));
            }
            #pragma unroll
            for (int ni = 0; ni < 4; ni++) {
                int n = wn + ni * 8 + gq;
                b[ni][0] = *(const float*)(tB + SMOFF(n, kk0));
                b[ni][1] = *(const float*)(tB + SMOFF(n, kk1));
            }
            #pragma unroll
            for (int mi = 0; mi < 4; mi++)
                #pragma unroll
                for (int ni = 0; ni < 4; ni++)
                    MMA_TF32(c[mi][ni], a[mi], b[ni]);
        }
        __syncthreads();
        if (t + 2 < T) issue(t + 2);
        CP_COMMIT();
    }

    // ---------------- epilogue: regs -> (+bias) -> GMEM ----------------
    float* oplane = outp + (long)gate * gateStride;
    #pragma unroll
    for (int mi = 0; mi < 4; mi++) {
        int r0 = rowBase + wm + mi * 16 + gq;
        int bb = r0 >> 9;                          // batch (S = 512)
        #pragma unroll
        for (int ni = 0; ni < 4; ni++) {
            int col = colBase + wn + ni * 8 + 2 * t4;
            float b0 = 0.0f, b1 = 0.0f;
            if (biasrow) {
                const float* bp = biasrow + ((long)gate * Bn + bb) * Hn + col;
                b0 = bp[0]; b1 = bp[1];
            }
            float2 v0 = make_float2(c[mi][ni][0] + b0, c[mi][ni][1] + b1);
            float2 v1 = make_float2(c[mi][ni][2] + b0, c[mi][ni][3] + b1);
            *(float2*)(oplane + (long)r0 * 512 + col)       = v0;
            *(float2*)(oplane + (long)(r0 + 8) * 512 + col) = v1;
        }
    }
}

// ---------------- column mean over sequence ---------------------------------------
__global__ void colmean_kernel(const float* __restrict__ in, float* __restrict__ out)
{
    int id = blockIdx.x * blockDim.x + threadIdx.x;
    if (id >= Bn * Hn) return;
    int b = id >> 9, k = id & 511;
    const float* p = in + (long)b * Sn * Hn + k;
    float s = 0.0f;
    #pragma unroll 8
    for (int t = 0; t < Sn; t++) s += p[(long)t * Hn];
    out[id] = s * (1.0f / (float)Sn);
}

// ---------------- small matmuls on dummy_h/combined (B=32 rows) --------------------
__global__ __launch_bounds__(512)
void smallmm_kernel(const float* __restrict__ dh, const float* __restrict__ comb,
                    const float* __restrict__ gW, const float* __restrict__ gb,
                    const float* __restrict__ Wd, const float* __restrict__ bvec,
                    float* __restrict__ gd, float* __restrict__ go,
                    float* __restrict__ dgf, float* __restrict__ biasrow)
{
    const int task = blockIdx.x, b = blockIdx.y, k = threadIdx.x;
    __shared__ float xs[512];
    __shared__ float ys[512];
    xs[k] = dh[b * Hn + k];
    if (task < 2) ys[k] = comb[b * Hn + k];
    __syncthreads();
    const int MM = Hn * Hn;
    if (task == 0) {
        const float* W1 = gW;          const float* W2 = gW + MM;
        float acc = gb[k];
        #pragma unroll 8
        for (int i = 0; i < Hn; i++) acc += xs[i] * W1[i * Hn + k] + ys[i] * W2[i * Hn + k];
        gd[b * Hn + k] = sigf(acc);
    } else if (task == 1) {
        const float* W1 = gW + 2 * MM; const float* W2 = gW + 3 * MM;
        float acc = gb[Hn + k];
        #pragma unroll 8
        for (int i = 0; i < Hn; i++) acc += xs[i] * W1[i * Hn + k] + ys[i] * W2[i * Hn + k];
        go[b * Hn + k] = sigf(acc);
    } else if (task == 2) {
        const float* W1 = gW + 4 * MM;
        float acc = gb[2 * Hn + k];
        #pragma unroll 8
        for (int i = 0; i < Hn; i++) acc += xs[i] * W1[i * Hn + k];
        dgf[b * Hn + k] = acc;
    } else {
        int g = task - 3;
        const float* W1 = Wd + (long)g * MM;
        float acc = bvec[g * Hn + k];
        #pragma unroll 8
        for (int i = 0; i < Hn; i++) acc += xs[i] * W1[i * Hn + k];
        biasrow[(g * Bn + b) * Hn + k] = acc;
    }
}

// ---------------- scores softmax over S+1 and dummy state update -------------------
__global__ void scorereduce_kernel(const float* __restrict__ gfz, const float* __restrict__ dgf,
                                   const float* __restrict__ gd, const float* __restrict__ go,
                                   const float* __restrict__ c, const float* __restrict__ dcold,
                                   float* __restrict__ dcnew, float* __restrict__ dhnew)
{
    int id = blockIdx.x * blockDim.x + threadIdx.x;
    if (id >= Bn * Hn) return;
    int b = id >> 9, k = id & 511;
    float add = dgf[id];
    float num = 0.0f, den = 0.0f;
    long base = ((long)b * Sn) * Hn + k;
    for (int s = 0; s < Sn; s++) {
        long idx = base + (long)s * Hn;
        float e = expf(sigf(gfz[idx] + add));
        num += e * c[idx];
        den += e;
    }
    float eg = expf(gd[id]);
    num += eg * dcold[id];
    den += eg;
    float dcn = num / den;
    dcnew[id] = dcn;
    dhnew[id] = go[id] * tanhf(dcn);
}

// ---------------- build Xbig slots [0:2048) = [h | hb | ha | sw_h] (tf32-rounded) --
__global__ void buildxcat_kernel(const float* __restrict__ h, const int* __restrict__ pos,
                                 float* __restrict__ X)
{
    long id = (long)blockIdx.x * blockDim.x + threadIdx.x;
    if (id >= (long)Nn * Hn) return;
    int n = (int)(id >> 9), k = (int)(id & 511);
    int b = n >> 9, s = n & 511;
    long hb_base = (long)n * Hn + k;
    float hv = h[hb_base];
    float hb = (s >= 1 ? h[hb_base - Hn] : 0.0f) + (s >= 2 ? h[hb_base - 2 * Hn] : 0.0f);
    float ha = (s <= Sn - 2 ? h[hb_base + Hn] : 0.0f) + (s <= Sn - 3 ? h[hb_base + 2 * Hn] : 0.0f);
    int p = pos[n];
    float sw = (p > 0) ? h[((long)((b << 9) + p - 1)) * Hn + k] : 0.0f;
    long xo = (long)n * KBIG + k;
    X[xo]         = tf32r(hv);
    X[xo + 512]   = tf32r(hb);
    X[xo + 1024]  = tf32r(ha);
    X[xo + 1536]  = tf32r(sw);
}

// ---------------- emb slot of Xbig (once) ------------------------------------------
__global__ void copyemb_kernel(const float* __restrict__ w, float* __restrict__ X)
{
    long id = (long)blockIdx.x * blockDim.x + threadIdx.x;
    if (id >= (long)Nn * WDn) return;
    int n = (int)(id >> 9), k = (int)(id & 511);
    X[(long)n * KBIG + 2048 + k] = tf32r(w[id]);
}

// ---------------- Wbig[c][k] (K-major, tf32-rounded) + gWT -------------------------
__global__ void buildw_kernel(const float* __restrict__ Wx, const float* __restrict__ Wh,
                              const float* __restrict__ Ws, const float* __restrict__ Wi,
                              float* __restrict__ W)
{
    long id = (long)blockIdx.x * blockDim.x + threadIdx.x;
    if (id >= (long)NTOT * KBIG) return;
    int k = (int)(id % KBIG);
    int c = (int)(id / KBIG);
    int g = c >> 9, hcol = c & 511;
    float v;
    if (k < 512)        v = Wx[((long)g * 512  + k)          * Hn + hcol];
    else if (k < 1536)  v = Wh[((long)g * 1024 + (k - 512))  * Hn + hcol];
    else if (k < 2048)  v = Ws[((long)g * 512  + (k - 1536)) * Hn + hcol];
    else                v = Wi[((long)g * 512  + (k - 2048)) * Hn + hcol];
    W[id] = tf32r(v);
}
__global__ void buildgwt_kernel(const float* __restrict__ gW, float* __restrict__ WT)
{
    int id = blockIdx.x * blockDim.x + threadIdx.x;
    if (id >= Hn * Hn) return;
    int c = id >> 9, k = id & 511;
    WT[id] = tf32r(gW[5 * Hn * Hn + k * Hn + c]);
}

// ---------------- gate combine ------------------------------------------------------
__global__ void combine_kernel(const float* __restrict__ Z, const float* __restrict__ c_in,
                               const int* __restrict__ pos, const float* __restrict__ dcold,
                               float* __restrict__ h_out, float* __restrict__ c_out)
{
    long id = (long)blockIdx.x * blockDim.x + threadIdx.x;
    if (id >= (long)Nn * Hn) return;
    int n = (int)(id >> 9), k = (int)(id & 511);
    int b = n >> 9, s = n & 511;
    const long gs = (long)Nn * Hn;
    float z[8];
    #pragma unroll
    for (int g = 0; g < 8; g++) z[g] = Z[(long)g * gs + id];
    float es[6], sum = 0.0f;
    #pragma unroll
    for (int i = 0; i < 6; i++) { es[i] = expf(sigf(z[i])); sum += es[i]; }
    float inv = 1.0f / sum;
    long cb_base = (long)n * Hn + k;
    float cb = (s >= 1 ? c_in[cb_base - Hn] : 0.0f) + (s >= 2 ? c_in[cb_base - 2 * Hn] : 0.0f);
    float ca = (s <= Sn - 2 ? c_in[cb_base + Hn] : 0.0f) + (s <= Sn - 3 ? c_in[cb_base + 2 * Hn] : 0.0f);
    int p = pos[n];
    float swc = (p > 0) ? c_in[((long)((b << 9) + p - 1)) * Hn + k] : 0.0f;
    float cf  = c_in[cb_base];
    float tdc = dcold[(b << 9) + k];
    float u = tanhf(z[7]);
    float o = sigf(z[6]);
    float cn = (es[0] * cb + es[1] * ca + es[2] * cf + es[3] * tdc + es[4] * swc + es[5] * u) * inv;
    c_out[id] = cn;
    h_out[id] = o * tanhf(cn);
}

// =====================================================================================
extern "C" void kernel_launch(void* const* d_in, const int* in_sizes, int n_in,
                              void* d_out, int out_size)
{
    const float* word_inputs = (const float*)d_in[0];
    const float* init_h      = (const float*)d_in[1];
    const float* init_c      = (const float*)d_in[2];
    const float* Wx          = (const float*)d_in[3];
    const float* Wh          = (const float*)d_in[4];
    const float* Wi          = (const float*)d_in[5];
    const float* Wd          = (const float*)d_in[6];
    const float* Ws          = (const float*)d_in[7];
    const float* bvec        = (const float*)d_in[8];
    const float* gW          = (const float*)d_in[9];
    const float* gb          = (const float*)d_in[10];
    const int*   postab      = (const int*)d_in[11];
    float* out = (float*)d_out;

    float *Zb, *Xbig, *Wbig, *gWT, *hA, *hB, *cA, *cB, *gfz;
    float *dh, *dc, *comb, *gd, *go, *dgf, *biasrow;
    cudaGetSymbolAddress((void**)&Zb,      g_Z);
    cudaGetSymbolAddress((void**)&Xbig,    g_Xbig);
    cudaGetSymbolAddress((void**)&Wbig,    g_Wbig);
    cudaGetSymbolAddress((void**)&gWT,     g_gWT);
    cudaGetSymbolAddress((void**)&hA,      g_hA);
    cudaGetSymbolAddress((void**)&hB,      g_hB);
    cudaGetSymbolAddress((void**)&cA,      g_cA);
    cudaGetSymbolAddress((void**)&cB,      g_cB);
    cudaGetSymbolAddress((void**)&gfz,     g_gfz);
    cudaGetSymbolAddress((void**)&dh,      g_dh);
    cudaGetSymbolAddress((void**)&dc,      g_dc);
    cudaGetSymbolAddress((void**)&comb,    g_comb);
    cudaGetSymbolAddress((void**)&gd,      g_gd);
    cudaGetSymbolAddress((void**)&go,      g_go);
    cudaGetSymbolAddress((void**)&dgf,     g_dgf);
    cudaGetSymbolAddress((void**)&biasrow, g_biasrow);

    cudaFuncSetAttribute(mmagemm, cudaFuncAttributeMaxDynamicSharedMemorySize, GEMM_SMEM);

    const long stateBytes = (long)Nn * Hn * sizeof(float);

    // ---- init ----
    cudaMemcpyAsync(hA, init_h, stateBytes, cudaMemcpyDeviceToDevice);
    cudaMemcpyAsync(cA, init_c, stateBytes, cudaMemcpyDeviceToDevice);
    colmean_kernel<<<64, 256>>>(init_h, dh + 0);
    colmean_kernel<<<64, 256>>>(init_c, dc + 0);
    buildw_kernel<<<(int)(((long)NTOT * KBIG + 255) / 256), 256>>>(Wx, Wh, Ws, Wi, Wbig);
    buildgwt_kernel<<<(Hn * Hn) / 256, 256>>>(gW, gWT);
    copyemb_kernel<<<(int)(((long)Nn * WDn) / 256), 256>>>(word_inputs, Xbig);

    for (int L = 0; L < NUM_LAYERS; L++) {
        const float* h_in = (L & 1) ? hB : hA;
        const float* c_in = (L & 1) ? cB : cA;
        float* h_out = (L == NUM_LAYERS - 1) ? out : ((L & 1) ? hA : hB);
        float* c_out = (L & 1) ? cA : cB;
        float* dh_in  = dh + (L & 1) * (Bn * Hn);
        float* dh_out = dh + (1 - (L & 1)) * (Bn * Hn);
        float* dc_in  = dc + (L & 1) * (Bn * Hn);
        float* dc_out = dc + (1 - (L & 1)) * (Bn * Hn);

        colmean_kernel<<<64, 256>>>(h_in, comb);
        smallmm_kernel<<<dim3(11, Bn), 512>>>(dh_in, comb, gW, gb, Wd, bvec,
                                              gd, go, dgf, biasrow);
        // gfz = h @ gWhf   (tensor core; h is fp32, tf32-truncation in HW is fine here)
        mmagemm<<<dim3(4, Nn / 128, 1), 256, GEMM_SMEM>>>(h_in, Hn, gWT, Hn,
                                                          gfz, 0, nullptr);
        scorereduce_kernel<<<64, 256>>>(gfz, dgf, gd, go, c_in, dc_in, dc_out, dh_out);
        buildxcat_kernel<<<(int)(((long)Nn * Hn) / 256), 256>>>(h_in, postab, Xbig);
        // Z[g] = Xbig @ Wbig[g] + biasrow[g]   (emb folded into K)
        mmagemm<<<dim3(4, Nn / 128, NGn), 256, GEMM_SMEM>>>(Xbig, KBIG, Wbig, KBIG,
                                                            Zb, GS, biasrow);
        combine_kernel<<<(int)(((long)Nn * Hn) / 256), 256>>>(Zb, c_in, postab, dc_in,
                                                              h_out, c_out);
    }
}

// round 7
// speedup vs baseline: 3.7021x; 1.1696x over previous
#include <cuda_runtime.h>
#include <cuda_bf16.h>
#include <math.h>
#include <stdint.h>

// Problem constants
#define Bn   32
#define Sn   512
#define Hn   512
#define WDn  512
#define Nn   (Bn * Sn)        // 16384 tokens
#define NGn  8
#define KBIG 2560             // [h | hb | ha | sw_h | emb]
#define NTOT 4096             // 8 gates * 512
#define NUM_LAYERS 4

static const long GS = (long)Nn * Hn;  // 8,388,608 elems per gate-plane

// ---------------- scratch (device globals; no allocations allowed) ----------------
__device__ float g_Z[(long)NGn * Nn * Hn];         // 256 MB : gate pre-activations
__device__ float g_Xbig[(long)Nn * KBIG];          // 160 MB : [h | hb | ha | sw_h | emb]
__device__ float g_Wbig[(long)NTOT * KBIG];        //  40 MB : K-major weights
__device__ float g_gWT[(long)Hn * Hn];             //   1 MB : gWhf transposed (K-major)
__device__ float g_hA[(long)Nn * Hn];
__device__ float g_hB[(long)Nn * Hn];
__device__ float g_cA[(long)Nn * Hn];
__device__ float g_cB[(long)Nn * Hn];
__device__ float g_gfz[(long)Nn * Hn];
__device__ float g_dh[2][Bn * Hn];
__device__ float g_dc[2][Bn * Hn];
__device__ float g_comb[Bn * Hn];
__device__ float g_gd[Bn * Hn];
__device__ float g_go[Bn * Hn];
__device__ float g_dgf[Bn * Hn];
__device__ float g_biasrow[NGn * Bn * Hn];         // td_h @ Wd[g] + b[g]

__device__ __forceinline__ float sigf(float x) { return 1.0f / (1.0f + expf(-x)); }
__device__ __forceinline__ float tf32r(float x) {
    uint32_t u; asm("cvt.rna.tf32.f32 %0, %1;" : "=r"(u) : "f"(x));
    return __uint_as_float(u);
}

// ======================= PTX helpers =====================================
__device__ __forceinline__ uint32_t smem_u32(const void* p) {
    uint32_t a;
    asm("{ .reg .u64 t; cvta.to.shared.u64 t, %1; cvt.u32.u64 %0, t; }" : "=r"(a) : "l"(p));
    return a;
}
#define CP_ASYNC16(dst, src) \
    asm volatile("cp.async.cg.shared.global [%0], [%1], 16;" \
        :: "r"(dst), "l"(__cvta_generic_to_global(src)))
#define CP_COMMIT()   asm volatile("cp.async.commit_group;" ::: "memory")
#define CP_WAIT(N)    asm volatile("cp.async.wait_group %0;" :: "n"(N) : "memory")

// m16n8k8 tf32 mma, row.col, f32 accum
#define MMA_TF32(d, a, b) \
    asm volatile("mma.sync.aligned.m16n8k8.row.col.f32.tf32.tf32.f32 " \
        "{%0,%1,%2,%3},{%4,%5,%6,%7},{%8,%9},{%0,%1,%2,%3};" \
        : "+f"((d)[0]), "+f"((d)[1]), "+f"((d)[2]), "+f"((d)[3]) \
        : "r"(__float_as_uint((a)[0])), "r"(__float_as_uint((a)[1])), \
          "r"(__float_as_uint((a)[2])), "r"(__float_as_uint((a)[3])), \
          "r"(__float_as_uint((b)[0])), "r"(__float_as_uint((b)[1])))

// smem tile: row-major [rows][32 k floats], XOR-swizzled 16B chunks.
#define SMOFF(m, kk) ((m) * 128 + ((((kk) >> 2) ^ ((m) & 7)) << 4) + (((kk) & 3) << 2))

// ======================= mma.sync tf32 tensor-core GEMM ============================
// D[m, col] = sum_k A[m,k] * Bw[gate*512 + col, k]
// CTA tile 128(M) x 256(N), 8 warps of 64x64, 3-stage cp.async pipeline.
#define STAGES 3
#define STAGE_B (16384 + 32768)           // A 16KB + B 32KB = 48KB
#define GEMM_SMEM (STAGES * STAGE_B)

__global__ __launch_bounds__(256, 1)
void mmagemm(const float* __restrict__ A, int lda,
             const float* __restrict__ Bw, int Kel,
             float* __restrict__ outp, long gateStride,
             const float* __restrict__ biasrow)
{
    extern __shared__ char sm[];
    const int tid = threadIdx.x, wid = tid >> 5, lane = tid & 31;
    const int gq = lane >> 2, t4 = lane & 3;
    const int rowBase = blockIdx.y * 128;
    const int colBase = blockIdx.x * 256;          // within 512
    const int gate = blockIdx.z;
    const float* Aorig = A  + (long)rowBase * lda;
    const float* Borig = Bw + ((long)gate * 512 + colBase) * Kel;
    const int T = Kel >> 5;                        // K chunks of 32
    const int wm = (wid & 1) * 64, wn = (wid >> 1) * 64;

    float c[4][8][4];
    #pragma unroll
    for (int i = 0; i < 4; i++)
        #pragma unroll
        for (int j = 0; j < 8; j++)
            #pragma unroll
            for (int q = 0; q < 4; q++) c[i][j][q] = 0.0f;

    auto issue = [&](int t) {
        const int s = t % STAGES;
        const uint32_t sA = smem_u32(sm) + s * STAGE_B;
        const uint32_t sB = sA + 16384;
        const long k0 = (long)t * 32;
        #pragma unroll
        for (int i = 0; i < 4; i++) {              // A: 1024 chunks of 16B
            int chunk = i * 256 + tid;
            int m = chunk >> 3, ch = chunk & 7;
            CP_ASYNC16(sA + m * 128 + ((ch ^ (m & 7)) << 4),
                       Aorig + (long)m * lda + k0 + ch * 4);
        }
        #pragma unroll
        for (int i = 0; i < 8; i++) {              // B: 2048 chunks of 16B
            int chunk = i * 256 + tid;
            int n = chunk >> 3, ch = chunk & 7;
            CP_ASYNC16(sB + n * 128 + ((ch ^ (n & 7)) << 4),
                       Borig + (long)n * Kel + k0 + ch * 4);
        }
    };

    issue(0); CP_COMMIT();
    issue(1); CP_COMMIT();

    for (int t = 0; t < T; t++) {
        CP_WAIT(1);
        __syncthreads();
        if (t + 2 < T) issue(t + 2);
        CP_COMMIT();
        const int s = t % STAGES;
        const char* tA = sm + s * STAGE_B;
        const char* tB = tA + 16384;
        #pragma unroll
        for (int ks = 0; ks < 4; ks++) {
            const int k8 = ks * 8;
            const int kk0 = k8 + t4, kk1 = k8 + t4 + 4;
            float a[4][4], b[8][2];
            #pragma unroll
            for (int mi = 0; mi < 4; mi++) {
                int m = wm + mi * 16 + gq;
                a[mi][0] = *(const float*)(tA + SMOFF(m,     kk0));
                a[mi][1] = *(const float*)(tA + SMOFF(m + 8, kk0));
                a[mi][2] = *(const float*)(tA + SMOFF(m,     kk1));
                a[mi][3] = *(const float*)(tA + SMOFF(m + 8, kk1));
            }
            #pragma unroll
            for (int ni = 0; ni < 8; ni++) {
                int n = wn + ni * 8 + gq;
                b[ni][0] = *(const float*)(tB + SMOFF(n, kk0));
                b[ni][1] = *(const float*)(tB + SMOFF(n, kk1));
            }
            #pragma unroll
            for (int mi = 0; mi < 4; mi++)
                #pragma unroll
                for (int ni = 0; ni < 8; ni++)
                    MMA_TF32(c[mi][ni], a[mi], b[ni]);
        }
    }

    // ---------------- epilogue: regs -> (+bias) -> GMEM ----------------
    float* oplane = outp + (long)gate * gateStride;
    #pragma unroll
    for (int mi = 0; mi < 4; mi++) {
        int r0 = rowBase + wm + mi * 16 + gq;
        int bb = r0 >> 9;                          // batch (S = 512)
        #pragma unroll
        for (int ni = 0; ni < 8; ni++) {
            int col = colBase + wn + ni * 8 + 2 * t4;
            float b0 = 0.0f, b1 = 0.0f;
            if (biasrow) {
                const float* bp = biasrow + ((long)gate * Bn + bb) * Hn + col;
                b0 = bp[0]; b1 = bp[1];
            }
            float2 v0 = make_float2(c[mi][ni][0] + b0, c[mi][ni][1] + b1);
            float2 v1 = make_float2(c[mi][ni][2] + b0, c[mi][ni][3] + b1);
            *(float2*)(oplane + (long)r0 * 512 + col)       = v0;
            *(float2*)(oplane + (long)(r0 + 8) * 512 + col) = v1;
        }
    }
}

// ---------------- column mean over sequence (8-way s-split) ------------------------
// grid (Hn/32, Bn), block 256 = 8 sgroups x 32 lanes
__global__ void colmean_kernel(const float* __restrict__ in, float* __restrict__ out)
{
    const int sg = threadIdx.x >> 5, kl = threadIdx.x & 31;
    const int b = blockIdx.y, k = blockIdx.x * 32 + kl;
    __shared__ float red[8][32];
    const float* p = in + ((long)b * Sn + sg * 64) * Hn + k;
    float s = 0.0f;
    #pragma unroll 8
    for (int t = 0; t < 64; t++) s += p[(long)t * Hn];
    red[sg][kl] = s;
    __syncthreads();
    if (sg == 0) {
        float tot = 0.0f;
        #pragma unroll
        for (int i = 0; i < 8; i++) tot += red[i][kl];
        out[b * Hn + k] = tot * (1.0f / (float)Sn);
    }
}

// ---------------- small matmuls on dummy_h/combined (B=32 rows) --------------------
__global__ __launch_bounds__(512)
void smallmm_kernel(const float* __restrict__ dh, const float* __restrict__ comb,
                    const float* __restrict__ gW, const float* __restrict__ gb,
                    const float* __restrict__ Wd, const float* __restrict__ bvec,
                    float* __restrict__ gd, float* __restrict__ go,
                    float* __restrict__ dgf, float* __restrict__ biasrow)
{
    const int task = blockIdx.x, b = blockIdx.y, k = threadIdx.x;
    __shared__ float xs[512];
    __shared__ float ys[512];
    xs[k] = dh[b * Hn + k];
    if (task < 2) ys[k] = comb[b * Hn + k];
    __syncthreads();
    const int MM = Hn * Hn;
    if (task == 0) {
        const float* W1 = gW;          const float* W2 = gW + MM;
        float acc = gb[k];
        #pragma unroll 8
        for (int i = 0; i < Hn; i++) acc += xs[i] * W1[i * Hn + k] + ys[i] * W2[i * Hn + k];
        gd[b * Hn + k] = sigf(acc);
    } else if (task == 1) {
        const float* W1 = gW + 2 * MM; const float* W2 = gW + 3 * MM;
        float acc = gb[Hn + k];
        #pragma unroll 8
        for (int i = 0; i < Hn; i++) acc += xs[i] * W1[i * Hn + k] + ys[i] * W2[i * Hn + k];
        go[b * Hn + k] = sigf(acc);
    } else if (task == 2) {
        const float* W1 = gW + 4 * MM;
        float acc = gb[2 * Hn + k];
        #pragma unroll 8
        for (int i = 0; i < Hn; i++) acc += xs[i] * W1[i * Hn + k];
        dgf[b * Hn + k] = acc;
    } else {
        int g = task - 3;
        const float* W1 = Wd + (long)g * MM;
        float acc = bvec[g * Hn + k];
        #pragma unroll 8
        for (int i = 0; i < Hn; i++) acc += xs[i] * W1[i * Hn + k];
        biasrow[(g * Bn + b) * Hn + k] = acc;
    }
}

// ---------------- scores softmax over S+1 and dummy state update -------------------
// grid (Hn/32, Bn), block 256 = 8 sgroups x 32 lanes
__global__ void scorereduce_kernel(const float* __restrict__ gfz, const float* __restrict__ dgf,
                                   const float* __restrict__ gd, const float* __restrict__ go,
                                   const float* __restrict__ c, const float* __restrict__ dcold,
                                   float* __restrict__ dcnew, float* __restrict__ dhnew)
{
    const int sg = threadIdx.x >> 5, kl = threadIdx.x & 31;
    const int b = blockIdx.y, k = blockIdx.x * 32 + kl;
    const int id = b * Hn + k;
    __shared__ float rnum[8][32], rden[8][32];
    const float add = dgf[id];
    const float* gp = gfz + ((long)b * Sn + sg * 64) * Hn + k;
    const float* cp = c   + ((long)b * Sn + sg * 64) * Hn + k;
    float num = 0.0f, den = 0.0f;
    #pragma unroll 4
    for (int t = 0; t < 64; t++) {
        float e = expf(sigf(gp[(long)t * Hn] + add));
        num += e * cp[(long)t * Hn];
        den += e;
    }
    rnum[sg][kl] = num; rden[sg][kl] = den;
    __syncthreads();
    if (sg == 0) {
        float tn = 0.0f, td = 0.0f;
        #pragma unroll
        for (int i = 0; i < 8; i++) { tn += rnum[i][kl]; td += rden[i][kl]; }
        float eg = expf(gd[id]);
        tn += eg * dcold[id];
        td += eg;
        float dcn = tn / td;
        dcnew[id] = dcn;
        dhnew[id] = go[id] * tanhf(dcn);
    }
}

// ---------------- build Xbig slots [0:2048) = [h | hb | ha | sw_h] (tf32-rounded) --
__global__ void buildxcat_kernel(const float* __restrict__ h, const int* __restrict__ pos,
                                 float* __restrict__ X)
{
    long id = (long)blockIdx.x * blockDim.x + threadIdx.x;
    if (id >= (long)Nn * Hn) return;
    int n = (int)(id >> 9), k = (int)(id & 511);
    int b = n >> 9, s = n & 511;
    long hb_base = (long)n * Hn + k;
    float hv = h[hb_base];
    float hb = (s >= 1 ? h[hb_base - Hn] : 0.0f) + (s >= 2 ? h[hb_base - 2 * Hn] : 0.0f);
    float ha = (s <= Sn - 2 ? h[hb_base + Hn] : 0.0f) + (s <= Sn - 3 ? h[hb_base + 2 * Hn] : 0.0f);
    int p = pos[n];
    float sw = (p > 0) ? h[((long)((b << 9) + p - 1)) * Hn + k] : 0.0f;
    long xo = (long)n * KBIG + k;
    X[xo]         = tf32r(hv);
    X[xo + 512]   = tf32r(hb);
    X[xo + 1024]  = tf32r(ha);
    X[xo + 1536]  = tf32r(sw);
}

// ---------------- emb slot of Xbig (once) ------------------------------------------
__global__ void copyemb_kernel(const float* __restrict__ w, float* __restrict__ X)
{
    long id = (long)blockIdx.x * blockDim.x + threadIdx.x;
    if (id >= (long)Nn * WDn) return;
    int n = (int)(id >> 9), k = (int)(id & 511);
    X[(long)n * KBIG + 2048 + k] = tf32r(w[id]);
}

// ---------------- Wbig[c][k] (K-major, tf32-rounded) + gWT -------------------------
__global__ void buildw_kernel(const float* __restrict__ Wx, const float* __restrict__ Wh,
                              const float* __restrict__ Ws, const float* __restrict__ Wi,
                              float* __restrict__ W)
{
    long id = (long)blockIdx.x * blockDim.x + threadIdx.x;
    if (id >= (long)NTOT * KBIG) return;
    int k = (int)(id % KBIG);
    int c = (int)(id / KBIG);
    int g = c >> 9, hcol = c & 511;
    float v;
    if (k < 512)        v = Wx[((long)g * 512  + k)          * Hn + hcol];
    else if (k < 1536)  v = Wh[((long)g * 1024 + (k - 512))  * Hn + hcol];
    else if (k < 2048)  v = Ws[((long)g * 512  + (k - 1536)) * Hn + hcol];
    else                v = Wi[((long)g * 512  + (k - 2048)) * Hn + hcol];
    W[id] = tf32r(v);
}
__global__ void buildgwt_kernel(const float* __restrict__ gW, float* __restrict__ WT)
{
    int id = blockIdx.x * blockDim.x + threadIdx.x;
    if (id >= Hn * Hn) return;
    int c = id >> 9, k = id & 511;
    WT[id] = tf32r(gW[5 * Hn * Hn + k * Hn + c]);
}

// ---------------- gate combine ------------------------------------------------------
__global__ void combine_kernel(const float* __restrict__ Z, const float* __restrict__ c_in,
                               const int* __restrict__ pos, const float* __restrict__ dcold,
                               float* __restrict__ h_out, float* __restrict__ c_out)
{
    long id = (long)blockIdx.x * blockDim.x + threadIdx.x;
    if (id >= (long)Nn * Hn) return;
    int n = (int)(id >> 9), k = (int)(id & 511);
    int b = n >> 9, s = n & 511;
    const long gs = (long)Nn * Hn;
    float z[8];
    #pragma unroll
    for (int g = 0; g < 8; g++) z[g] = Z[(long)g * gs + id];
    float es[6], sum = 0.0f;
    #pragma unroll
    for (int i = 0; i < 6; i++) { es[i] = expf(sigf(z[i])); sum += es[i]; }
    float inv = 1.0f / sum;
    long cb_base = (long)n * Hn + k;
    float cb = (s >= 1 ? c_in[cb_base - Hn] : 0.0f) + (s >= 2 ? c_in[cb_base - 2 * Hn] : 0.0f);
    float ca = (s <= Sn - 2 ? c_in[cb_base + Hn] : 0.0f) + (s <= Sn - 3 ? c_in[cb_base + 2 * Hn] : 0.0f);
    int p = pos[n];
    float swc = (p > 0) ? c_in[((long)((b << 9) + p - 1)) * Hn + k] : 0.0f;
    float cf  = c_in[cb_base];
    float tdc = dcold[(b << 9) + k];
    float u = tanhf(z[7]);
    float o = sigf(z[6]);
    float cn = (es[0] * cb + es[1] * ca + es[2] * cf + es[3] * tdc + es[4] * swc + es[5] * u) * inv;
    c_out[id] = cn;
    h_out[id] = o * tanhf(cn);
}

// =====================================================================================
extern "C" void kernel_launch(void* const* d_in, const int* in_sizes, int n_in,
                              void* d_out, int out_size)
{
    const float* word_inputs = (const float*)d_in[0];
    const float* init_h      = (const float*)d_in[1];
    const float* init_c      = (const float*)d_in[2];
    const float* Wx          = (const float*)d_in[3];
    const float* Wh          = (const float*)d_in[4];
    const float* Wi          = (const float*)d_in[5];
    const float* Wd          = (const float*)d_in[6];
    const float* Ws          = (const float*)d_in[7];
    const float* bvec        = (const float*)d_in[8];
    const float* gW          = (const float*)d_in[9];
    const float* gb          = (const float*)d_in[10];
    const int*   postab      = (const int*)d_in[11];
    float* out = (float*)d_out;

    float *Zb, *Xbig, *Wbig, *gWT, *hA, *hB, *cA, *cB, *gfz;
    float *dh, *dc, *comb, *gd, *go, *dgf, *biasrow;
    cudaGetSymbolAddress((void**)&Zb,      g_Z);
    cudaGetSymbolAddress((void**)&Xbig,    g_Xbig);
    cudaGetSymbolAddress((void**)&Wbig,    g_Wbig);
    cudaGetSymbolAddress((void**)&gWT,     g_gWT);
    cudaGetSymbolAddress((void**)&hA,      g_hA);
    cudaGetSymbolAddress((void**)&hB,      g_hB);
    cudaGetSymbolAddress((void**)&cA,      g_cA);
    cudaGetSymbolAddress((void**)&cB,      g_cB);
    cudaGetSymbolAddress((void**)&gfz,     g_gfz);
    cudaGetSymbolAddress((void**)&dh,      g_dh);
    cudaGetSymbolAddress((void**)&dc,      g_dc);
    cudaGetSymbolAddress((void**)&comb,    g_comb);
    cudaGetSymbolAddress((void**)&gd,      g_gd);
    cudaGetSymbolAddress((void**)&go,      g_go);
    cudaGetSymbolAddress((void**)&dgf,     g_dgf);
    cudaGetSymbolAddress((void**)&biasrow, g_biasrow);

    cudaFuncSetAttribute(mmagemm, cudaFuncAttributeMaxDynamicSharedMemorySize, GEMM_SMEM);

    const long stateBytes = (long)Nn * Hn * sizeof(float);

    // ---- init ----
    cudaMemcpyAsync(hA, init_h, stateBytes, cudaMemcpyDeviceToDevice);
    cudaMemcpyAsync(cA, init_c, stateBytes, cudaMemcpyDeviceToDevice);
    colmean_kernel<<<dim3(Hn / 32, Bn), 256>>>(init_h, dh + 0);
    colmean_kernel<<<dim3(Hn / 32, Bn), 256>>>(init_c, dc + 0);
    buildw_kernel<<<(int)(((long)NTOT * KBIG + 255) / 256), 256>>>(Wx, Wh, Ws, Wi, Wbig);
    buildgwt_kernel<<<(Hn * Hn) / 256, 256>>>(gW, gWT);
    copyemb_kernel<<<(int)(((long)Nn * WDn) / 256), 256>>>(word_inputs, Xbig);

    for (int L = 0; L < NUM_LAYERS; L++) {
        const float* h_in = (L & 1) ? hB : hA;
        const float* c_in = (L & 1) ? cB : cA;
        float* h_out = (L == NUM_LAYERS - 1) ? out : ((L & 1) ? hA : hB);
        float* c_out = (L & 1) ? cA : cB;
        float* dh_in  = dh + (L & 1) * (Bn * Hn);
        float* dh_out = dh + (1 - (L & 1)) * (Bn * Hn);
        float* dc_in  = dc + (L & 1) * (Bn * Hn);
        float* dc_out = dc + (1 - (L & 1)) * (Bn * Hn);

        colmean_kernel<<<dim3(Hn / 32, Bn), 256>>>(h_in, comb);
        smallmm_kernel<<<dim3(11, Bn), 512>>>(dh_in, comb, gW, gb, Wd, bvec,
                                              gd, go, dgf, biasrow);
        // gfz = h @ gWhf   (tensor core)
        mmagemm<<<dim3(2, Nn / 128, 1), 256, GEMM_SMEM>>>(h_in, Hn, gWT, Hn,
                                                          gfz, 0, nullptr);
        scorereduce_kernel<<<dim3(Hn / 32, Bn), 256>>>(gfz, dgf, gd, go, c_in,
                                                       dc_in, dc_out, dh_out);
        buildxcat_kernel<<<(int)(((long)Nn * Hn) / 256), 256>>>(h_in, postab, Xbig);
        // Z[g] = Xbig @ Wbig[g] + biasrow[g]   (emb folded into K)
        mmagemm<<<dim3(2, Nn / 128, NGn), 256, GEMM_SMEM>>>(Xbig, KBIG, Wbig, KBIG,
                                                            Zb, GS, biasrow);
        combine_kernel<<<(int)(((long)Nn * Hn) / 256), 256>>>(Zb, c_in, postab, dc_in,
                                                              h_out, c_out);
    }
}

// round 10
// speedup vs baseline: 6.5057x; 1.7573x over previous
#include <cuda_runtime.h>
#include <cuda_fp16.h>
#include <math.h>
#include <stdint.h>

// Problem constants
#define Bn   32
#define Sn   512
#define Hn   512
#define WDn  512
#define Nn   (Bn * Sn)        // 16384 tokens
#define NGn  8
#define KBIG 2560             // [h | hb | ha | sw_h | emb]
#define NTOT 4096             // 8 gates * 512
#define NUM_LAYERS 4

static const long GS = (long)Nn * Hn;  // 8,388,608 elems per gate-plane

// ---------------- scratch (device globals; no allocations allowed) ----------------
__device__ float  g_Z[(long)NGn * Nn * Hn];        // 256 MB : gate pre-activations
__device__ __half g_Xbig[(long)Nn * KBIG];         //  80 MB : [h | hb | ha | sw_h | emb]
__device__ __half g_Wbig[(long)NTOT * KBIG];       //  20 MB : K-major weights (fp16)
__device__ __half g_gWT[(long)Hn * Hn];            // 0.5 MB : gWhf transposed (K-major)
__device__ float  g_hA[(long)Nn * Hn];
__device__ float  g_hB[(long)Nn * Hn];
__device__ float  g_cA[(long)Nn * Hn];
__device__ float  g_cB[(long)Nn * Hn];
__device__ float  g_gfz[(long)Nn * Hn];
__device__ float  g_dh[2][Bn * Hn];
__device__ float  g_dc[2][Bn * Hn];
__device__ float  g_comb[Bn * Hn];
__device__ float  g_gd[Bn * Hn];
__device__ float  g_go[Bn * Hn];
__device__ float  g_dgf[Bn * Hn];
__device__ float  g_biasrow[NGn * Bn * Hn];        // td_h @ Wd[g] + b[g]

__device__ __forceinline__ float sigf(float x) { return 1.0f / (1.0f + expf(-x)); }

// ======================= PTX helpers =====================================
__device__ __forceinline__ uint32_t smem_u32(const void* p) {
    uint32_t a;
    asm("{ .reg .u64 t; cvta.to.shared.u64 t, %1; cvt.u32.u64 %0, t; }" : "=r"(a) : "l"(p));
    return a;
}
#define CP_ASYNC16(dst, src) \
    asm volatile("cp.async.cg.shared.global [%0], [%1], 16;" \
        :: "r"(dst), "l"(__cvta_generic_to_global(src)))
#define CP_COMMIT()   asm volatile("cp.async.commit_group;" ::: "memory")
#define CP_WAIT(N)    asm volatile("cp.async.wait_group %0;" :: "n"(N) : "memory")

// m16n8k16 fp16 mma, row.col, f32 accum. a: 4 x b32 (8 halves), b: 2 x b32.
#define MMA_F16(d, a, b) \
    asm volatile("mma.sync.aligned.m16n8k16.row.col.f32.f16.f16.f32 " \
        "{%0,%1,%2,%3},{%4,%5,%6,%7},{%8,%9},{%0,%1,%2,%3};" \
        : "+f"((d)[0]), "+f"((d)[1]), "+f"((d)[2]), "+f"((d)[3]) \
        : "r"((a)[0]), "r"((a)[1]), "r"((a)[2]), "r"((a)[3]), \
          "r"((b)[0]), "r"((b)[1]))

// smem tile: row-major [rows][64 k halves] = 128B/row, XOR-swizzled 16B chunks.
// byte offset of half (row m, k index kk):
#define SMOFFH(m, kk) ((m) * 128 + ((((kk) >> 3) ^ ((m) & 7)) << 4) + (((kk) & 7) << 1))

// ======================= mma.sync fp16 tensor-core GEMM ============================
// D[m, col] = sum_k A[m,k] * Bw[gate*512 + col, k]   (A, Bw fp16 K-major; D fp32)
// CTA tile 128(M) x 256(N), 8 warps of 64x64, 3-stage cp.async pipeline, K-chunk 64.
#define STAGES 3
#define A_BYTES 16384                     // 128 rows * 128 B
#define B_BYTES 32768                     // 256 rows * 128 B
#define STAGE_B (A_BYTES + B_BYTES)       // 48 KB
#define GEMM_SMEM (STAGES * STAGE_B)      // 144 KB

__global__ __launch_bounds__(256, 1)
void mmagemm(const __half* __restrict__ A, int lda,
             const __half* __restrict__ Bw, int Kel,
             float* __restrict__ outp, long gateStride,
             const float* __restrict__ biasrow)
{
    extern __shared__ char sm[];
    const int tid = threadIdx.x, wid = tid >> 5, lane = tid & 31;
    const int gq = lane >> 2, t4 = lane & 3;
    const int rowBase = blockIdx.y * 128;
    const int colBase = blockIdx.x * 256;          // within 512
    const int gate = blockIdx.z;
    const __half* Aorig = A  + (long)rowBase * lda;
    const __half* Borig = Bw + ((long)gate * 512 + colBase) * Kel;
    const int T = Kel >> 6;                        // K chunks of 64
    const int wm = (wid & 1) * 64, wn = (wid >> 1) * 64;

    float c[4][8][4];
    #pragma unroll
    for (int i = 0; i < 4; i++)
        #pragma unroll
        for (int j = 0; j < 8; j++)
            #pragma unroll
            for (int q = 0; q < 4; q++) c[i][j][q] = 0.0f;

    auto issue = [&](int t) {
        const int s = t % STAGES;
        const uint32_t sA = smem_u32(sm) + s * STAGE_B;
        const uint32_t sB = sA + A_BYTES;
        const long k0 = (long)t * 64;
        #pragma unroll
        for (int i = 0; i < 4; i++) {              // A: 128 rows x 8 chunks = 1024
            int chunk = i * 256 + tid;
            int m = chunk >> 3, ch = chunk & 7;
            CP_ASYNC16(sA + m * 128 + ((ch ^ (m & 7)) << 4),
                       Aorig + (long)m * lda + k0 + ch * 8);
        }
        #pragma unroll
        for (int i = 0; i < 8; i++) {              // B: 256 rows x 8 chunks = 2048
            int chunk = i * 256 + tid;
            int n = chunk >> 3, ch = chunk & 7;
            CP_ASYNC16(sB + n * 128 + ((ch ^ (n & 7)) << 4),
                       Borig + (long)n * Kel + k0 + ch * 8);
        }
    };

    issue(0); CP_COMMIT();
    issue(1); CP_COMMIT();

    for (int t = 0; t < T; t++) {
        CP_WAIT(1);
        __syncthreads();
        if (t + 2 < T) issue(t + 2);
        CP_COMMIT();
        const int s = t % STAGES;
        const char* tA = sm + s * STAGE_B;
        const char* tB = tA + A_BYTES;
        #pragma unroll
        for (int ks = 0; ks < 4; ks++) {
            const int k16 = ks * 16;
            const int klo = k16 + t4 * 2, khi = k16 + 8 + t4 * 2;
            uint32_t a[4][4], b[8][2];
            #pragma unroll
            for (int mi = 0; mi < 4; mi++) {
                int m = wm + mi * 16 + gq;
                a[mi][0] = *(const uint32_t*)(tA + SMOFFH(m,     klo));
                a[mi][1] = *(const uint32_t*)(tA + SMOFFH(m + 8, klo));
                a[mi][2] = *(const uint32_t*)(tA + SMOFFH(m,     khi));
                a[mi][3] = *(const uint32_t*)(tA + SMOFFH(m + 8, khi));
            }
            #pragma unroll
            for (int ni = 0; ni < 8; ni++) {
                int n = wn + ni * 8 + gq;
                b[ni][0] = *(const uint32_t*)(tB + SMOFFH(n, klo));
                b[ni][1] = *(const uint32_t*)(tB + SMOFFH(n, khi));
            }
            #pragma unroll
            for (int mi = 0; mi < 4; mi++)
                #pragma unroll
                for (int ni = 0; ni < 8; ni++)
                    MMA_F16(c[mi][ni], a[mi], b[ni]);
        }
    }

    // ---------------- epilogue: regs -> (+bias) -> GMEM ----------------
    float* oplane = outp + (long)gate * gateStride;
    #pragma unroll
    for (int mi = 0; mi < 4; mi++) {
        int r0 = rowBase + wm + mi * 16 + gq;
        int bb = r0 >> 9;                          // batch (S = 512)
        #pragma unroll
        for (int ni = 0; ni < 8; ni++) {
            int col = colBase + wn + ni * 8 + 2 * t4;
            float b0 = 0.0f, b1 = 0.0f;
            if (biasrow) {
                const float* bp = biasrow + ((long)gate * Bn + bb) * Hn + col;
                b0 = bp[0]; b1 = bp[1];
            }
            float2 v0 = make_float2(c[mi][ni][0] + b0, c[mi][ni][1] + b1);
            float2 v1 = make_float2(c[mi][ni][2] + b0, c[mi][ni][3] + b1);
            *(float2*)(oplane + (long)r0 * 512 + col)       = v0;
            *(float2*)(oplane + (long)(r0 + 8) * 512 + col) = v1;
        }
    }
}

// ---------------- column mean over sequence (8-way s-split) ------------------------
__global__ void colmean_kernel(const float* __restrict__ in, float* __restrict__ out)
{
    const int sg = threadIdx.x >> 5, kl = threadIdx.x & 31;
    const int b = blockIdx.y, k = blockIdx.x * 32 + kl;
    __shared__ float red[8][32];
    const float* p = in + ((long)b * Sn + sg * 64) * Hn + k;
    float s = 0.0f;
    #pragma unroll 8
    for (int t = 0; t < 64; t++) s += p[(long)t * Hn];
    red[sg][kl] = s;
    __syncthreads();
    if (sg == 0) {
        float tot = 0.0f;
        #pragma unroll
        for (int i = 0; i < 8; i++) tot += red[i][kl];
        out[b * Hn + k] = tot * (1.0f / (float)Sn);
    }
}

// ---------------- small matmuls on dummy_h/combined (B=32 rows) --------------------
__global__ __launch_bounds__(512)
void smallmm_kernel(const float* __restrict__ dh, const float* __restrict__ comb,
                    const float* __restrict__ gW, const float* __restrict__ gb,
                    const float* __restrict__ Wd, const float* __restrict__ bvec,
                    float* __restrict__ gd, float* __restrict__ go,
                    float* __restrict__ dgf, float* __restrict__ biasrow)
{
    const int task = blockIdx.x, b = blockIdx.y, k = threadIdx.x;
    __shared__ float xs[512];
    __shared__ float ys[512];
    xs[k] = dh[b * Hn + k];
    if (task < 2) ys[k] = comb[b * Hn + k];
    __syncthreads();
    const int MM = Hn * Hn;
    if (task == 0) {
        const float* W1 = gW;          const float* W2 = gW + MM;
        float acc = gb[k];
        #pragma unroll 8
        for (int i = 0; i < Hn; i++) acc += xs[i] * W1[i * Hn + k] + ys[i] * W2[i * Hn + k];
        gd[b * Hn + k] = sigf(acc);
    } else if (task == 1) {
        const float* W1 = gW + 2 * MM; const float* W2 = gW + 3 * MM;
        float acc = gb[Hn + k];
        #pragma unroll 8
        for (int i = 0; i < Hn; i++) acc += xs[i] * W1[i * Hn + k] + ys[i] * W2[i * Hn + k];
        go[b * Hn + k] = sigf(acc);
    } else if (task == 2) {
        const float* W1 = gW + 4 * MM;
        float acc = gb[2 * Hn + k];
        #pragma unroll 8
        for (int i = 0; i < Hn; i++) acc += xs[i] * W1[i * Hn + k];
        dgf[b * Hn + k] = acc;
    } else {
        int g = task - 3;
        const float* W1 = Wd + (long)g * MM;
        float acc = bvec[g * Hn + k];
        #pragma unroll 8
        for (int i = 0; i < Hn; i++) acc += xs[i] * W1[i * Hn + k];
        biasrow[(g * Bn + b) * Hn + k] = acc;
    }
}

// ---------------- scores softmax over S+1 and dummy state update -------------------
__global__ void scorereduce_kernel(const float* __restrict__ gfz, const float* __restrict__ dgf,
                                   const float* __restrict__ gd, const float* __restrict__ go,
                                   const float* __restrict__ c, const float* __restrict__ dcold,
                                   float* __restrict__ dcnew, float* __restrict__ dhnew)
{
    const int sg = threadIdx.x >> 5, kl = threadIdx.x & 31;
    const int b = blockIdx.y, k = blockIdx.x * 32 + kl;
    const int id = b * Hn + k;
    __shared__ float rnum[8][32], rden[8][32];
    const float add = dgf[id];
    const float* gp = gfz + ((long)b * Sn + sg * 64) * Hn + k;
    const float* cp = c   + ((long)b * Sn + sg * 64) * Hn + k;
    float num = 0.0f, den = 0.0f;
    #pragma unroll 4
    for (int t = 0; t < 64; t++) {
        float e = expf(sigf(gp[(long)t * Hn] + add));
        num += e * cp[(long)t * Hn];
        den += e;
    }
    rnum[sg][kl] = num; rden[sg][kl] = den;
    __syncthreads();
    if (sg == 0) {
        float tn = 0.0f, td = 0.0f;
        #pragma unroll
        for (int i = 0; i < 8; i++) { tn += rnum[i][kl]; td += rden[i][kl]; }
        float eg = expf(gd[id]);
        tn += eg * dcold[id];
        td += eg;
        float dcn = tn / td;
        dcnew[id] = dcn;
        dhnew[id] = go[id] * tanhf(dcn);
    }
}

// ---------------- build Xbig slots [0:2048) = [h | hb | ha | sw_h] (fp16) ----------
__global__ void buildxcat_kernel(const float* __restrict__ h, const int* __restrict__ pos,
                                 __half* __restrict__ X)
{
    long id = (long)blockIdx.x * blockDim.x + threadIdx.x;
    if (id >= (long)Nn * Hn) return;
    int n = (int)(id >> 9), k = (int)(id & 511);
    int b = n >> 9, s = n & 511;
    long hb_base = (long)n * Hn + k;
    float hv = h[hb_base];
    float hb = (s >= 1 ? h[hb_base - Hn] : 0.0f) + (s >= 2 ? h[hb_base - 2 * Hn] : 0.0f);
    float ha = (s <= Sn - 2 ? h[hb_base + Hn] : 0.0f) + (s <= Sn - 3 ? h[hb_base + 2 * Hn] : 0.0f);
    int p = pos[n];
    float sw = (p > 0) ? h[((long)((b << 9) + p - 1)) * Hn + k] : 0.0f;
    long xo = (long)n * KBIG + k;
    X[xo]         = __float2half_rn(hv);
    X[xo + 512]   = __float2half_rn(hb);
    X[xo + 1024]  = __float2half_rn(ha);
    X[xo + 1536]  = __float2half_rn(sw);
}

// ---------------- emb slot of Xbig (once) ------------------------------------------
__global__ void copyemb_kernel(const float* __restrict__ w, __half* __restrict__ X)
{
    long id = (long)blockIdx.x * blockDim.x + threadIdx.x;
    if (id >= (long)Nn * WDn) return;
    int n = (int)(id >> 9), k = (int)(id & 511);
    X[(long)n * KBIG + 2048 + k] = __float2half_rn(w[id]);
}

// ---------------- Wbig[c][k] (K-major fp16) + gWT ----------------------------------
__global__ void buildw_kernel(const float* __restrict__ Wx, const float* __restrict__ Wh,
                              const float* __restrict__ Ws, const float* __restrict__ Wi,
                              __half* __restrict__ W)
{
    long id = (long)blockIdx.x * blockDim.x + threadIdx.x;
    if (id >= (long)NTOT * KBIG) return;
    int k = (int)(id % KBIG);
    int c = (int)(id / KBIG);
    int g = c >> 9, hcol = c & 511;
    float v;
    if (k < 512)        v = Wx[((long)g * 512  + k)          * Hn + hcol];
    else if (k < 1536)  v = Wh[((long)g * 1024 + (k - 512))  * Hn + hcol];
    else if (k < 2048)  v = Ws[((long)g * 512  + (k - 1536)) * Hn + hcol];
    else                v = Wi[((long)g * 512  + (k - 2048)) * Hn + hcol];
    W[id] = __float2half_rn(v);
}
__global__ void buildgwt_kernel(const float* __restrict__ gW, __half* __restrict__ WT)
{
    int id = blockIdx.x * blockDim.x + threadIdx.x;
    if (id >= Hn * Hn) return;
    int c = id >> 9, k = id & 511;
    WT[id] = __float2half_rn(gW[5 * Hn * Hn + k * Hn + c]);
}

// ---------------- gate combine ------------------------------------------------------
__global__ void combine_kernel(const float* __restrict__ Z, const float* __restrict__ c_in,
                               const int* __restrict__ pos, const float* __restrict__ dcold,
                               float* __restrict__ h_out, float* __restrict__ c_out)
{
    long id = (long)blockIdx.x * blockDim.x + threadIdx.x;
    if (id >= (long)Nn * Hn) return;
    int n = (int)(id >> 9), k = (int)(id & 511);
    int b = n >> 9, s = n & 511;
    const long gs = (long)Nn * Hn;
    float z[8];
    #pragma unroll
    for (int g = 0; g < 8; g++) z[g] = Z[(long)g * gs + id];
    float es[6], sum = 0.0f;
    #pragma unroll
    for (int i = 0; i < 6; i++) { es[i] = expf(sigf(z[i])); sum += es[i]; }
    float inv = 1.0f / sum;
    long cb_base = (long)n * Hn + k;
    float cb = (s >= 1 ? c_in[cb_base - Hn] : 0.0f) + (s >= 2 ? c_in[cb_base - 2 * Hn] : 0.0f);
    float ca = (s <= Sn - 2 ? c_in[cb_base + Hn] : 0.0f) + (s <= Sn - 3 ? c_in[cb_base + 2 * Hn] : 0.0f);
    int p = pos[n];
    float swc = (p > 0) ? c_in[((long)((b << 9) + p - 1)) * Hn + k] : 0.0f;
    float cf  = c_in[cb_base];
    float tdc = dcold[(b << 9) + k];
    float u = tanhf(z[7]);
    float o = sigf(z[6]);
    float cn = (es[0] * cb + es[1] * ca + es[2] * cf + es[3] * tdc + es[4] * swc + es[5] * u) * inv;
    c_out[id] = cn;
    h_out[id] = o * tanhf(cn);
}

// =====================================================================================
extern "C" void kernel_launch(void* const* d_in, const int* in_sizes, int n_in,
                              void* d_out, int out_size)
{
    const float* word_inputs = (const float*)d_in[0];
    const float* init_h      = (const float*)d_in[1];
    const float* init_c      = (const float*)d_in[2];
    const float* Wx          = (const float*)d_in[3];
    const float* Wh          = (const float*)d_in[4];
    const float* Wi          = (const float*)d_in[5];
    const float* Wd          = (const float*)d_in[6];
    const float* Ws          = (const float*)d_in[7];
    const float* bvec        = (const float*)d_in[8];
    const float* gW          = (const float*)d_in[9];
    const float* gb          = (const float*)d_in[10];
    const int*   postab      = (const int*)d_in[11];
    float* out = (float*)d_out;

    float *Zb, *hA, *hB, *cA, *cB, *gfz;
    float *dh, *dc, *comb, *gd, *go, *dgf, *biasrow;
    __half *Xbig, *Wbig, *gWT;
    cudaGetSymbolAddress((void**)&Zb,      g_Z);
    cudaGetSymbolAddress((void**)&Xbig,    g_Xbig);
    cudaGetSymbolAddress((void**)&Wbig,    g_Wbig);
    cudaGetSymbolAddress((void**)&gWT,     g_gWT);
    cudaGetSymbolAddress((void**)&hA,      g_hA);
    cudaGetSymbolAddress((void**)&hB,      g_hB);
    cudaGetSymbolAddress((void**)&cA,      g_cA);
    cudaGetSymbolAddress((void**)&cB,      g_cB);
    cudaGetSymbolAddress((void**)&gfz,     g_gfz);
    cudaGetSymbolAddress((void**)&dh,      g_dh);
    cudaGetSymbolAddress((void**)&dc,      g_dc);
    cudaGetSymbolAddress((void**)&comb,    g_comb);
    cudaGetSymbolAddress((void**)&gd,      g_gd);
    cudaGetSymbolAddress((void**)&go,      g_go);
    cudaGetSymbolAddress((void**)&dgf,     g_dgf);
    cudaGetSymbolAddress((void**)&biasrow, g_biasrow);

    cudaFuncSetAttribute(mmagemm, cudaFuncAttributeMaxDynamicSharedMemorySize, GEMM_SMEM);

    const long stateBytes = (long)Nn * Hn * sizeof(float);

    // ---- init ----
    cudaMemcpyAsync(hA, init_h, stateBytes, cudaMemcpyDeviceToDevice);
    cudaMemcpyAsync(cA, init_c, stateBytes, cudaMemcpyDeviceToDevice);
    colmean_kernel<<<dim3(Hn / 32, Bn), 256>>>(init_h, dh + 0);
    colmean_kernel<<<dim3(Hn / 32, Bn), 256>>>(init_c, dc + 0);
    buildw_kernel<<<(int)(((long)NTOT * KBIG + 255) / 256), 256>>>(Wx, Wh, Ws, Wi, Wbig);
    buildgwt_kernel<<<(Hn * Hn) / 256, 256>>>(gW, gWT);
    copyemb_kernel<<<(int)(((long)Nn * WDn) / 256), 256>>>(word_inputs, Xbig);

    for (int L = 0; L < NUM_LAYERS; L++) {
        const float* h_in = (L & 1) ? hB : hA;
        const float* c_in = (L & 1) ? cB : cA;
        float* h_out = (L == NUM_LAYERS - 1) ? out : ((L & 1) ? hA : hB);
        float* c_out = (L & 1) ? cA : cB;
        float* dh_in  = dh + (L & 1) * (Bn * Hn);
        float* dh_out = dh + (1 - (L & 1)) * (Bn * Hn);
        float* dc_in  = dc + (L & 1) * (Bn * Hn);
        float* dc_out = dc + (1 - (L & 1)) * (Bn * Hn);

        colmean_kernel<<<dim3(Hn / 32, Bn), 256>>>(h_in, comb);
        smallmm_kernel<<<dim3(11, Bn), 512>>>(dh_in, comb, gW, gb, Wd, bvec,
                                              gd, go, dgf, biasrow);
        // Xbig = [h | hb | ha | sw_h] fp16 (emb slot persistent)
        buildxcat_kernel<<<(int)(((long)Nn * Hn) / 256), 256>>>(h_in, postab, Xbig);
        // gfz = h @ gWhf  (A = Xbig slot 0, lda = KBIG)
        mmagemm<<<dim3(2, Nn / 128, 1), 256, GEMM_SMEM>>>(Xbig, KBIG, gWT, Hn,
                                                          gfz, 0, nullptr);
        scorereduce_kernel<<<dim3(Hn / 32, Bn), 256>>>(gfz, dgf, gd, go, c_in,
                                                       dc_in, dc_out, dh_out);
        // Z[g] = Xbig @ Wbig[g] + biasrow[g]
        mmagemm<<<dim3(2, Nn / 128, NGn), 256, GEMM_SMEM>>>(Xbig, KBIG, Wbig, KBIG,
                                                            Zb, GS, biasrow);
        combine_kernel<<<(int)(((long)Nn * Hn) / 256), 256>>>(Zb, c_in, postab, dc_in,
                                                              h_out, c_out);
    }
}

// round 12
// speedup vs baseline: 6.7240x; 1.0336x over previous
#include <cuda_runtime.h>
#include <cuda_fp16.h>
#include <math.h>
#include <stdint.h>

// Problem constants
#define Bn   32
#define Sn   512
#define Hn   512
#define WDn  512
#define Nn   (Bn * Sn)        // 16384 tokens
#define NGn  8
#define KBIG 2560             // [h | hb | ha | sw_h | emb]
#define NTOT 4096             // 8 gates * 512
#define NUM_LAYERS 4

static const long GS2 = (long)Nn * 256;  // half2 elems per gate-plane

// ---------------- scratch (device globals; no allocations allowed) ----------------
__device__ __half g_Z[(long)NGn * Nn * Hn];        // 128 MB : gate pre-activations (fp16)
__device__ __half g_Xbig[(long)Nn * KBIG];         //  80 MB : [h | hb | ha | sw_h | emb]
__device__ __half g_Wbig[(long)NTOT * KBIG];       //  20 MB : K-major weights (fp16)
__device__ __half g_gWT[(long)Hn * Hn];            // 0.5 MB : gWhf transposed (K-major)
__device__ float  g_hA[(long)Nn * Hn];
__device__ float  g_hB[(long)Nn * Hn];
__device__ float  g_cA[(long)Nn * Hn];
__device__ float  g_cB[(long)Nn * Hn];
__device__ float  g_gfz[(long)Nn * Hn];
__device__ float  g_dh[2][Bn * Hn];
__device__ float  g_dc[2][Bn * Hn];
__device__ float  g_comb[Bn * Hn];
__device__ float  g_gd[Bn * Hn];
__device__ float  g_go[Bn * Hn];
__device__ float  g_dgf[Bn * Hn];
__device__ float  g_biasrow[NGn * Bn * Hn];        // td_h @ Wd[g] + b[g]

__device__ __forceinline__ float sigf(float x) { return 1.0f / (1.0f + expf(-x)); }

// ======================= PTX helpers =====================================
__device__ __forceinline__ uint32_t smem_u32(const void* p) {
    uint32_t a;
    asm("{ .reg .u64 t; cvta.to.shared.u64 t, %1; cvt.u32.u64 %0, t; }" : "=r"(a) : "l"(p));
    return a;
}
#define CP_ASYNC16(dst, src) \
    asm volatile("cp.async.cg.shared.global [%0], [%1], 16;" \
        :: "r"(dst), "l"(__cvta_generic_to_global(src)))
#define CP_COMMIT()   asm volatile("cp.async.commit_group;" ::: "memory")
#define CP_WAIT(N)    asm volatile("cp.async.wait_group %0;" :: "n"(N) : "memory")

// m16n8k16 fp16 mma, row.col, f32 accum. a: 4 x b32, b: 2 x b32.
#define MMA_F16(d, a, b) \
    asm volatile("mma.sync.aligned.m16n8k16.row.col.f32.f16.f16.f32 " \
        "{%0,%1,%2,%3},{%4,%5,%6,%7},{%8,%9},{%0,%1,%2,%3};" \
        : "+f"((d)[0]), "+f"((d)[1]), "+f"((d)[2]), "+f"((d)[3]) \
        : "r"((a)[0]), "r"((a)[1]), "r"((a)[2]), "r"((a)[3]), \
          "r"((b)[0]), "r"((b)[1]))

#define LDSM_X4(r0, r1, r2, r3, addr) \
    asm volatile("ldmatrix.sync.aligned.m8n8.x4.shared.b16 {%0,%1,%2,%3}, [%4];" \
        : "=r"(r0), "=r"(r1), "=r"(r2), "=r"(r3) : "r"(addr))

// ======================= mma.sync fp16 tensor-core GEMM ============================
// D[m, col] = sum_k A[m,k] * Bw[gate*512 + col, k]   (A, Bw fp16 K-major)
// CTA tile 128(M) x 256(N), 8 warps of 64x64, 3-stage cp.async pipeline, K-chunk 64.
// smem rows: 128 B (64 halves), XOR-swizzled 16B chunks: chunk' = chunk ^ (row & 7).
#define STAGES 3
#define A_BYTES 16384                     // 128 rows * 128 B
#define B_BYTES 32768                     // 256 rows * 128 B
#define STAGE_B (A_BYTES + B_BYTES)       // 48 KB
#define GEMM_SMEM (STAGES * STAGE_B)      // 144 KB

template <bool HALF_OUT>
__global__ __launch_bounds__(256, 1)
void mmagemm(const __half* __restrict__ A, int lda,
             const __half* __restrict__ Bw, int Kel,
             void* __restrict__ outp, long gateStride,
             const float* __restrict__ biasrow)
{
    extern __shared__ char sm[];
    const int tid = threadIdx.x, wid = tid >> 5, lane = tid & 31;
    const int gq = lane >> 2, t4 = lane & 3;
    const int rowBase = blockIdx.y * 128;
    const int colBase = blockIdx.x * 256;          // within 512
    const int gate = blockIdx.z;
    const __half* Aorig = A  + (long)rowBase * lda;
    const __half* Borig = Bw + ((long)gate * 512 + colBase) * Kel;
    const int T = Kel >> 6;                        // K chunks of 64
    const int wm = (wid & 1) * 64, wn = (wid >> 1) * 64;

    // ldmatrix lane geometry (see analysis):
    // A tiles:  m = wm + mi*16 + ((lane>>3)&1)*8 + (lane&7),  khalf = lane>>4
    // B tiles:  n = wn + nip*16 + (lane>>4)*8 + (lane&7),     khalf = (lane>>3)&1
    const int mA_base = wm + ((lane >> 3) & 1) * 8 + (lane & 7);
    const int ghA = lane >> 4;
    const uint32_t m7a = (uint32_t)(mA_base & 7);
    const int nB_base = wn + (lane >> 4) * 8 + (lane & 7);
    const int ghB = (lane >> 3) & 1;
    const uint32_t n7b = (uint32_t)(nB_base & 7);
    uint32_t relA[4], relB[4];
    #pragma unroll
    for (int i = 0; i < 4; i++) {
        relA[i] = (uint32_t)(mA_base + i * 16) * 128u;
        relB[i] = (uint32_t)(nB_base + i * 16) * 128u + A_BYTES;
    }
    const uint32_t smbase = smem_u32(sm);

    float c[4][8][4];
    #pragma unroll
    for (int i = 0; i < 4; i++)
        #pragma unroll
        for (int j = 0; j < 8; j++)
            #pragma unroll
            for (int q = 0; q < 4; q++) c[i][j][q] = 0.0f;

    auto issue = [&](int t) {
        const int s = t % STAGES;
        const uint32_t sA = smbase + s * STAGE_B;
        const uint32_t sB = sA + A_BYTES;
        const long k0 = (long)t * 64;
        #pragma unroll
        for (int i = 0; i < 4; i++) {              // A: 128 rows x 8 chunks = 1024
            int chunk = i * 256 + tid;
            int m = chunk >> 3, ch = chunk & 7;
            CP_ASYNC16(sA + m * 128 + ((ch ^ (m & 7)) << 4),
                       Aorig + (long)m * lda + k0 + ch * 8);
        }
        #pragma unroll
        for (int i = 0; i < 8; i++) {              // B: 256 rows x 8 chunks = 2048
            int chunk = i * 256 + tid;
            int n = chunk >> 3, ch = chunk & 7;
            CP_ASYNC16(sB + n * 128 + ((ch ^ (n & 7)) << 4),
                       Borig + (long)n * Kel + k0 + ch * 8);
        }
    };

    issue(0); CP_COMMIT();
    issue(1); CP_COMMIT();

    for (int t = 0; t < T; t++) {
        CP_WAIT(1);
        __syncthreads();
        if (t + 2 < T) issue(t + 2);
        CP_COMMIT();
        const uint32_t stg = smbase + (t % STAGES) * STAGE_B;
        #pragma unroll
        for (int ks = 0; ks < 4; ks++) {
            const uint32_t sAo = ((((uint32_t)(ks << 1) + ghA) ^ m7a) << 4);
            const uint32_t sBo = ((((uint32_t)(ks << 1) + ghB) ^ n7b) << 4);
            uint32_t a[4][4], b[8][2];
            #pragma unroll
            for (int mi = 0; mi < 4; mi++)
                LDSM_X4(a[mi][0], a[mi][1], a[mi][2], a[mi][3],
                        stg + relA[mi] + sAo);
            #pragma unroll
            for (int nip = 0; nip < 4; nip++)
                LDSM_X4(b[2 * nip][0], b[2 * nip][1], b[2 * nip + 1][0], b[2 * nip + 1][1],
                        stg + relB[nip] + sBo);
            #pragma unroll
            for (int mi = 0; mi < 4; mi++)
                #pragma unroll
                for (int ni = 0; ni < 8; ni++)
                    MMA_F16(c[mi][ni], a[mi], b[ni]);
        }
    }

    // ---------------- epilogue: regs -> (+bias) -> GMEM ----------------
    const int bb = rowBase >> 9;                   // batch constant per CTA (S = 512)
    #pragma unroll
    for (int mi = 0; mi < 4; mi++) {
        int r0 = rowBase + wm + mi * 16 + gq;
        #pragma unroll
        for (int ni = 0; ni < 8; ni++) {
            int col = colBase + wn + ni * 8 + 2 * t4;
            float b0 = 0.0f, b1 = 0.0f;
            if (biasrow) {
                const float* bp = biasrow + ((long)gate * Bn + bb) * Hn + col;
                b0 = bp[0]; b1 = bp[1];
            }
            if (HALF_OUT) {
                __half* oplane = (__half*)outp + (long)gate * gateStride;
                *(__half2*)(oplane + (long)r0 * 512 + col) =
                    __floats2half2_rn(c[mi][ni][0] + b0, c[mi][ni][1] + b1);
                *(__half2*)(oplane + (long)(r0 + 8) * 512 + col) =
                    __floats2half2_rn(c[mi][ni][2] + b0, c[mi][ni][3] + b1);
            } else {
                float* oplane = (float*)outp + (long)gate * gateStride;
                *(float2*)(oplane + (long)r0 * 512 + col) =
                    make_float2(c[mi][ni][0] + b0, c[mi][ni][1] + b1);
                *(float2*)(oplane + (long)(r0 + 8) * 512 + col) =
                    make_float2(c[mi][ni][2] + b0, c[mi][ni][3] + b1);
            }
        }
    }
}

// ---------------- column mean over sequence (8-way s-split) ------------------------
__global__ void colmean_kernel(const float* __restrict__ in, float* __restrict__ out)
{
    const int sg = threadIdx.x >> 5, kl = threadIdx.x & 31;
    const int b = blockIdx.y, k = blockIdx.x * 32 + kl;
    __shared__ float red[8][32];
    const float* p = in + ((long)b * Sn + sg * 64) * Hn + k;
    float s = 0.0f;
    #pragma unroll 8
    for (int t = 0; t < 64; t++) s += p[(long)t * Hn];
    red[sg][kl] = s;
    __syncthreads();
    if (sg == 0) {
        float tot = 0.0f;
        #pragma unroll
        for (int i = 0; i < 8; i++) tot += red[i][kl];
        out[b * Hn + k] = tot * (1.0f / (float)Sn);
    }
}

// ---------------- small matmuls on dummy_h/combined (B=32 rows) --------------------
__global__ __launch_bounds__(512)
void smallmm_kernel(const float* __restrict__ dh, const float* __restrict__ comb,
                    const float* __restrict__ gW, const float* __restrict__ gb,
                    const float* __restrict__ Wd, const float* __restrict__ bvec,
                    float* __restrict__ gd, float* __restrict__ go,
                    float* __restrict__ dgf, float* __restrict__ biasrow)
{
    const int task = blockIdx.x, b = blockIdx.y, k = threadIdx.x;
    __shared__ float xs[512];
    __shared__ float ys[512];
    xs[k] = dh[b * Hn + k];
    if (task < 2) ys[k] = comb[b * Hn + k];
    __syncthreads();
    const int MM = Hn * Hn;
    if (task == 0) {
        const float* W1 = gW;          const float* W2 = gW + MM;
        float acc = gb[k];
        #pragma unroll 8
        for (int i = 0; i < Hn; i++) acc += xs[i] * W1[i * Hn + k] + ys[i] * W2[i * Hn + k];
        gd[b * Hn + k] = sigf(acc);
    } else if (task == 1) {
        const float* W1 = gW + 2 * MM; const float* W2 = gW + 3 * MM;
        float acc = gb[Hn + k];
        #pragma unroll 8
        for (int i = 0; i < Hn; i++) acc += xs[i] * W1[i * Hn + k] + ys[i] * W2[i * Hn + k];
        go[b * Hn + k] = sigf(acc);
    } else if (task == 2) {
        const float* W1 = gW + 4 * MM;
        float acc = gb[2 * Hn + k];
        #pragma unroll 8
        for (int i = 0; i < Hn; i++) acc += xs[i] * W1[i * Hn + k];
        dgf[b * Hn + k] = acc;
    } else {
        int g = task - 3;
        const float* W1 = Wd + (long)g * MM;
        float acc = bvec[g * Hn + k];
        #pragma unroll 8
        for (int i = 0; i < Hn; i++) acc += xs[i] * W1[i * Hn + k];
        biasrow[(g * Bn + b) * Hn + k] = acc;
    }
}

// ---------------- scores softmax over S+1 and dummy state update -------------------
__global__ void scorereduce_kernel(const float* __restrict__ gfz, const float* __restrict__ dgf,
                                   const float* __restrict__ gd, const float* __restrict__ go,
                                   const float* __restrict__ c, const float* __restrict__ dcold,
                                   float* __restrict__ dcnew, float* __restrict__ dhnew)
{
    const int sg = threadIdx.x >> 5, kl = threadIdx.x & 31;
    const int b = blockIdx.y, k = blockIdx.x * 32 + kl;
    const int id = b * Hn + k;
    __shared__ float rnum[8][32], rden[8][32];
    const float add = dgf[id];
    const float* gp = gfz + ((long)b * Sn + sg * 64) * Hn + k;
    const float* cp = c   + ((long)b * Sn + sg * 64) * Hn + k;
    float num = 0.0f, den = 0.0f;
    #pragma unroll 4
    for (int t = 0; t < 64; t++) {
        float e = expf(sigf(gp[(long)t * Hn] + add));
        num += e * cp[(long)t * Hn];
        den += e;
    }
    rnum[sg][kl] = num; rden[sg][kl] = den;
    __syncthreads();
    if (sg == 0) {
        float tn = 0.0f, td = 0.0f;
        #pragma unroll
        for (int i = 0; i < 8; i++) { tn += rnum[i][kl]; td += rden[i][kl]; }
        float eg = expf(gd[id]);
        tn += eg * dcold[id];
        td += eg;
        float dcn = tn / td;
        dcnew[id] = dcn;
        dhnew[id] = go[id] * tanhf(dcn);
    }
}

// ---------------- build Xbig slots [0:2048) = [h | hb | ha | sw_h] (fp16) ----------
__global__ void buildxcat_kernel(const float* __restrict__ h, const int* __restrict__ pos,
                                 __half* __restrict__ X)
{
    long id = (long)blockIdx.x * blockDim.x + threadIdx.x;
    if (id >= (long)Nn * Hn) return;
    int n = (int)(id >> 9), k = (int)(id & 511);
    int b = n >> 9, s = n & 511;
    long hb_base = (long)n * Hn + k;
    float hv = h[hb_base];
    float hb = (s >= 1 ? h[hb_base - Hn] : 0.0f) + (s >= 2 ? h[hb_base - 2 * Hn] : 0.0f);
    float ha = (s <= Sn - 2 ? h[hb_base + Hn] : 0.0f) + (s <= Sn - 3 ? h[hb_base + 2 * Hn] : 0.0f);
    int p = pos[n];
    float sw = (p > 0) ? h[((long)((b << 9) + p - 1)) * Hn + k] : 0.0f;
    long xo = (long)n * KBIG + k;
    X[xo]         = __float2half_rn(hv);
    X[xo + 512]   = __float2half_rn(hb);
    X[xo + 1024]  = __float2half_rn(ha);
    X[xo + 1536]  = __float2half_rn(sw);
}

// ---------------- emb slot of Xbig (once) ------------------------------------------
__global__ void copyemb_kernel(const float* __restrict__ w, __half* __restrict__ X)
{
    long id = (long)blockIdx.x * blockDim.x + threadIdx.x;
    if (id >= (long)Nn * WDn) return;
    int n = (int)(id >> 9), k = (int)(id & 511);
    X[(long)n * KBIG + 2048 + k] = __float2half_rn(w[id]);
}

// ---------------- Wbig[c][k] (K-major fp16) + gWT ----------------------------------
__global__ void buildw_kernel(const float* __restrict__ Wx, const float* __restrict__ Wh,
                              const float* __restrict__ Ws, const float* __restrict__ Wi,
                              __half* __restrict__ W)
{
    long id = (long)blockIdx.x * blockDim.x + threadIdx.x;
    if (id >= (long)NTOT * KBIG) return;
    int k = (int)(id % KBIG);
    int c = (int)(id / KBIG);
    int g = c >> 9, hcol = c & 511;
    float v;
    if (k < 512)        v = Wx[((long)g * 512  + k)          * Hn + hcol];
    else if (k < 1536)  v = Wh[((long)g * 1024 + (k - 512))  * Hn + hcol];
    else if (k < 2048)  v = Ws[((long)g * 512  + (k - 1536)) * Hn + hcol];
    else                v = Wi[((long)g * 512  + (k - 2048)) * Hn + hcol];
    W[id] = __float2half_rn(v);
}
__global__ void buildgwt_kernel(const float* __restrict__ gW, __half* __restrict__ WT)
{
    int id = blockIdx.x * blockDim.x + threadIdx.x;
    if (id >= Hn * Hn) return;
    int c = id >> 9, k = id & 511;
    WT[id] = __float2half_rn(gW[5 * Hn * Hn + k * Hn + c]);
}

// ---------------- gate combine (half2 Z, 2 elems/thread) ---------------------------
__global__ void combine_kernel(const __half2* __restrict__ Z2, const float* __restrict__ c_in,
                               const int* __restrict__ pos, const float* __restrict__ dcold,
                               float* __restrict__ h_out, float* __restrict__ c_out)
{
    long id = (long)blockIdx.x * blockDim.x + threadIdx.x;   // over Nn*256 pairs
    if (id >= (long)Nn * 256) return;
    int n = (int)(id >> 8), kp = (int)(id & 255);
    int k = kp * 2;
    int b = n >> 9, s = n & 511;
    const long gs2 = (long)Nn * 256;

    float2 z[8];
    #pragma unroll
    for (int g = 0; g < 8; g++) z[g] = __half22float2(Z2[(long)g * gs2 + id]);

    long base = (long)n * Hn + k;
    float2 cf = *(const float2*)(c_in + base);
    float2 cb = make_float2(0.f, 0.f), ca = make_float2(0.f, 0.f);
    if (s >= 1) { float2 v = *(const float2*)(c_in + base - Hn);     cb.x += v.x; cb.y += v.y; }
    if (s >= 2) { float2 v = *(const float2*)(c_in + base - 2 * Hn); cb.x += v.x; cb.y += v.y; }
    if (s <= Sn - 2) { float2 v = *(const float2*)(c_in + base + Hn);     ca.x += v.x; ca.y += v.y; }
    if (s <= Sn - 3) { float2 v = *(const float2*)(c_in + base + 2 * Hn); ca.x += v.x; ca.y += v.y; }
    int p = pos[n];
    float2 swc = make_float2(0.f, 0.f);
    if (p > 0) swc = *(const float2*)(c_in + ((long)((b << 9) + p - 1)) * Hn + k);
    float2 tdc = *(const float2*)(dcold + (b << 9) + k);

    float2 cn_o, hn_o;
    {   // elem 0
        float es[6], sum = 0.0f;
        float zz[8] = {z[0].x, z[1].x, z[2].x, z[3].x, z[4].x, z[5].x, z[6].x, z[7].x};
        #pragma unroll
        for (int i = 0; i < 6; i++) { es[i] = expf(sigf(zz[i])); sum += es[i]; }
        float inv = 1.0f / sum;
        float u = tanhf(zz[7]), o = sigf(zz[6]);
        float cn = (es[0] * cb.x + es[1] * ca.x + es[2] * cf.x + es[3] * tdc.x
                    + es[4] * swc.x + es[5] * u) * inv;
        cn_o.x = cn; hn_o.x = o * tanhf(cn);
    }
    {   // elem 1
        float es[6], sum = 0.0f;
        float zz[8] = {z[0].y, z[1].y, z[2].y, z[3].y, z[4].y, z[5].y, z[6].y, z[7].y};
        #pragma unroll
        for (int i = 0; i < 6; i++) { es[i] = expf(sigf(zz[i])); sum += es[i]; }
        float inv = 1.0f / sum;
        float u = tanhf(zz[7]), o = sigf(zz[6]);
        float cn = (es[0] * cb.y + es[1] * ca.y + es[2] * cf.y + es[3] * tdc.y
                    + es[4] * swc.y + es[5] * u) * inv;
        cn_o.y = cn; hn_o.y = o * tanhf(cn);
    }
    *(float2*)(c_out + base) = cn_o;
    *(float2*)(h_out + base) = hn_o;
}

// =====================================================================================
extern "C" void kernel_launch(void* const* d_in, const int* in_sizes, int n_in,
                              void* d_out, int out_size)
{
    const float* word_inputs = (const float*)d_in[0];
    const float* init_h      = (const float*)d_in[1];
    const float* init_c      = (const float*)d_in[2];
    const float* Wx          = (const float*)d_in[3];
    const float* Wh          = (const float*)d_in[4];
    const float* Wi          = (const float*)d_in[5];
    const float* Wd          = (const float*)d_in[6];
    const float* Ws          = (const float*)d_in[7];
    const float* bvec        = (const float*)d_in[8];
    const float* gW          = (const float*)d_in[9];
    const float* gb          = (const float*)d_in[10];
    const int*   postab      = (const int*)d_in[11];
    float* out = (float*)d_out;

    float *hA, *hB, *cA, *cB, *gfz;
    float *dh, *dc, *comb, *gd, *go, *dgf, *biasrow;
    __half *Zb, *Xbig, *Wbig, *gWT;
    cudaGetSymbolAddress((void**)&Zb,      g_Z);
    cudaGetSymbolAddress((void**)&Xbig,    g_Xbig);
    cudaGetSymbolAddress((void**)&Wbig,    g_Wbig);
    cudaGetSymbolAddress((void**)&gWT,     g_gWT);
    cudaGetSymbolAddress((void**)&hA,      g_hA);
    cudaGetSymbolAddress((void**)&hB,      g_hB);
    cudaGetSymbolAddress((void**)&cA,      g_cA);
    cudaGetSymbolAddress((void**)&cB,      g_cB);
    cudaGetSymbolAddress((void**)&gfz,     g_gfz);
    cudaGetSymbolAddress((void**)&dh,      g_dh);
    cudaGetSymbolAddress((void**)&dc,      g_dc);
    cudaGetSymbolAddress((void**)&comb,    g_comb);
    cudaGetSymbolAddress((void**)&gd,      g_gd);
    cudaGetSymbolAddress((void**)&go,      g_go);
    cudaGetSymbolAddress((void**)&dgf,     g_dgf);
    cudaGetSymbolAddress((void**)&biasrow, g_biasrow);

    cudaFuncSetAttribute(mmagemm<true>,  cudaFuncAttributeMaxDynamicSharedMemorySize, GEMM_SMEM);
    cudaFuncSetAttribute(mmagemm<false>, cudaFuncAttributeMaxDynamicSharedMemorySize, GEMM_SMEM);

    const long stateBytes = (long)Nn * Hn * sizeof(float);

    // ---- init ----
    cudaMemcpyAsync(hA, init_h, stateBytes, cudaMemcpyDeviceToDevice);
    cudaMemcpyAsync(cA, init_c, stateBytes, cudaMemcpyDeviceToDevice);
    colmean_kernel<<<dim3(Hn / 32, Bn), 256>>>(init_h, dh + 0);
    colmean_kernel<<<dim3(Hn / 32, Bn), 256>>>(init_c, dc + 0);
    buildw_kernel<<<(int)(((long)NTOT * KBIG + 255) / 256), 256>>>(Wx, Wh, Ws, Wi, Wbig);
    buildgwt_kernel<<<(Hn * Hn) / 256, 256>>>(gW, gWT);
    copyemb_kernel<<<(int)(((long)Nn * WDn) / 256), 256>>>(word_inputs, Xbig);

    for (int L = 0; L < NUM_LAYERS; L++) {
        const float* h_in = (L & 1) ? hB : hA;
        const float* c_in = (L & 1) ? cB : cA;
        float* h_out = (L == NUM_LAYERS - 1) ? out : ((L & 1) ? hA : hB);
        float* c_out = (L & 1) ? cA : cB;
        float* dh_in  = dh + (L & 1) * (Bn * Hn);
        float* dh_out = dh + (1 - (L & 1)) * (Bn * Hn);
        float* dc_in  = dc + (L & 1) * (Bn * Hn);
        float* dc_out = dc + (1 - (L & 1)) * (Bn * Hn);

        colmean_kernel<<<dim3(Hn / 32, Bn), 256>>>(h_in, comb);
        smallmm_kernel<<<dim3(11, Bn), 512>>>(dh_in, comb, gW, gb, Wd, bvec,
                                              gd, go, dgf, biasrow);
        // Xbig = [h | hb | ha | sw_h] fp16 (emb slot persistent)
        buildxcat_kernel<<<(int)(((long)Nn * Hn) / 256), 256>>>(h_in, postab, Xbig);
        // gfz = h @ gWhf  (A = Xbig slot 0, lda = KBIG; fp32 out)
        mmagemm<false><<<dim3(2, Nn / 128, 1), 256, GEMM_SMEM>>>(Xbig, KBIG, gWT, Hn,
                                                                 gfz, 0, nullptr);
        scorereduce_kernel<<<dim3(Hn / 32, Bn), 256>>>(gfz, dgf, gd, go, c_in,
                                                       dc_in, dc_out, dh_out);
        // Z[g] = Xbig @ Wbig[g] + biasrow[g]  (fp16 out)
        mmagemm<true><<<dim3(2, Nn / 128, NGn), 256, GEMM_SMEM>>>(Xbig, KBIG, Wbig, KBIG,
                                                                  Zb, GS2 * 2, biasrow);
        combine_kernel<<<(int)(((long)Nn * 256) / 256), 256>>>((const __half2*)Zb, c_in,
                                                               postab, dc_in, h_out, c_out);
    }
}

// round 13
// speedup vs baseline: 7.6124x; 1.1321x over previous
#include <cuda_runtime.h>
#include <cuda_fp16.h>
#include <math.h>
#include <stdint.h>

// Problem constants
#define Bn   32
#define Sn   512
#define Hn   512
#define WDn  512
#define Nn   (Bn * Sn)        // 16384 tokens
#define NGn  8
#define KBIG 2560             // [h | hb | ha | sw_h | emb]
#define NTOT 4096             // 8 gates * 512
#define NUM_LAYERS 4

static const long GS2 = (long)Nn * 256;  // half2 elems per gate-plane

// ---------------- scratch (device globals; no allocations allowed) ----------------
__device__ __half g_Z[(long)NGn * Nn * Hn];        // 128 MB : gate pre-activations (fp16)
__device__ __half g_Xbig[(long)Nn * KBIG];         //  80 MB : [h | hb | ha | sw_h | emb]
__device__ __half g_Wbig[(long)NTOT * KBIG];       //  20 MB : K-major weights (fp16)
__device__ __half g_gWT[(long)Hn * Hn];            // 0.5 MB : gWhf transposed (K-major)
__device__ float  g_hA[(long)Nn * Hn];
__device__ float  g_hB[(long)Nn * Hn];
__device__ float  g_cA[(long)Nn * Hn];
__device__ float  g_cB[(long)Nn * Hn];
__device__ float  g_gfz[(long)Nn * Hn];
__device__ float  g_dh[2][Bn * Hn];
__device__ float  g_dc[2][Bn * Hn];
__device__ float  g_comb[Bn * Hn];
__device__ float  g_gd[Bn * Hn];
__device__ float  g_go[Bn * Hn];
__device__ float  g_dgf[Bn * Hn];
__device__ float  g_biasrow[NGn * Bn * Hn];        // td_h @ Wd[g] + b[g]

__device__ __forceinline__ float sigf(float x) { return 1.0f / (1.0f + expf(-x)); }

// ======================= PTX helpers =====================================
__device__ __forceinline__ uint32_t smem_u32(const void* p) {
    uint32_t a;
    asm("{ .reg .u64 t; cvta.to.shared.u64 t, %1; cvt.u32.u64 %0, t; }" : "=r"(a) : "l"(p));
    return a;
}
#define CP_ASYNC16(dst, src) \
    asm volatile("cp.async.cg.shared.global [%0], [%1], 16;" \
        :: "r"(dst), "l"(__cvta_generic_to_global(src)))
#define CP_COMMIT()   asm volatile("cp.async.commit_group;" ::: "memory")
#define CP_WAIT(N)    asm volatile("cp.async.wait_group %0;" :: "n"(N) : "memory")

// m16n8k16 fp16 mma, row.col, f32 accum. a: 4 x b32, b: 2 x b32.
#define MMA_F16(d, a, b) \
    asm volatile("mma.sync.aligned.m16n8k16.row.col.f32.f16.f16.f32 " \
        "{%0,%1,%2,%3},{%4,%5,%6,%7},{%8,%9},{%0,%1,%2,%3};" \
        : "+f"((d)[0]), "+f"((d)[1]), "+f"((d)[2]), "+f"((d)[3]) \
        : "r"((a)[0]), "r"((a)[1]), "r"((a)[2]), "r"((a)[3]), \
          "r"((b)[0]), "r"((b)[1]))

#define LDSM_X4(r0, r1, r2, r3, addr) \
    asm volatile("ldmatrix.sync.aligned.m8n8.x4.shared.b16 {%0,%1,%2,%3}, [%4];" \
        : "=r"(r0), "=r"(r1), "=r"(r2), "=r"(r3) : "r"(addr))

// ======================= mma.sync fp16 tensor-core GEMM ============================
// D[m, col] = sum_k A[m,k] * Bw[gate*512 + col, k]   (A, Bw fp16 K-major)
// CTA tile 128(M) x 128(N), 4 warps of 64x64, 3-stage cp.async pipeline, K-chunk 64.
// 128 threads/CTA, 2 CTAs/SM (decoupled barriers hide pipeline bubbles).
// smem rows: 128 B (64 halves), XOR-swizzled 16B chunks: chunk' = chunk ^ (row & 7).
#define STAGES 3
#define A_BYTES 16384                     // 128 rows * 128 B
#define B_BYTES 16384                     // 128 rows * 128 B
#define STAGE_B (A_BYTES + B_BYTES)       // 32 KB
#define GEMM_SMEM (STAGES * STAGE_B)      // 96 KB

template <bool HALF_OUT>
__global__ __launch_bounds__(128, 2)
void mmagemm(const __half* __restrict__ A, int lda,
             const __half* __restrict__ Bw, int Kel,
             void* __restrict__ outp, long gateStride,
             const float* __restrict__ biasrow)
{
    extern __shared__ char sm[];
    const int tid = threadIdx.x, wid = tid >> 5, lane = tid & 31;
    const int gq = lane >> 2, t4 = lane & 3;
    const int rowBase = blockIdx.y * 128;
    const int colBase = blockIdx.x * 128;          // within 512
    const int gate = blockIdx.z;
    const __half* Aorig = A  + (long)rowBase * lda;
    const __half* Borig = Bw + ((long)gate * 512 + colBase) * Kel;
    const int T = Kel >> 6;                        // K chunks of 64
    const int wm = (wid & 1) * 64, wn = (wid >> 1) * 64;

    // ldmatrix lane geometry:
    // A tiles:  m = wm + mi*16 + ((lane>>3)&1)*8 + (lane&7),  khalf = lane>>4
    // B tiles:  n = wn + nip*16 + (lane>>4)*8 + (lane&7),     khalf = (lane>>3)&1
    const int mA_base = wm + ((lane >> 3) & 1) * 8 + (lane & 7);
    const int ghA = lane >> 4;
    const uint32_t m7a = (uint32_t)(mA_base & 7);
    const int nB_base = wn + (lane >> 4) * 8 + (lane & 7);
    const int ghB = (lane >> 3) & 1;
    const uint32_t n7b = (uint32_t)(nB_base & 7);
    uint32_t relA[4], relB[4];
    #pragma unroll
    for (int i = 0; i < 4; i++) {
        relA[i] = (uint32_t)(mA_base + i * 16) * 128u;
        relB[i] = (uint32_t)(nB_base + i * 16) * 128u + A_BYTES;
    }
    const uint32_t smbase = smem_u32(sm);

    float c[4][8][4];
    #pragma unroll
    for (int i = 0; i < 4; i++)
        #pragma unroll
        for (int j = 0; j < 8; j++)
            #pragma unroll
            for (int q = 0; q < 4; q++) c[i][j][q] = 0.0f;

    auto issue = [&](int t) {
        const int s = t % STAGES;
        const uint32_t sA = smbase + s * STAGE_B;
        const uint32_t sB = sA + A_BYTES;
        const long k0 = (long)t * 64;
        #pragma unroll
        for (int i = 0; i < 8; i++) {              // A: 128 rows x 8 chunks = 1024
            int chunk = i * 128 + tid;
            int m = chunk >> 3, ch = chunk & 7;
            CP_ASYNC16(sA + m * 128 + ((ch ^ (m & 7)) << 4),
                       Aorig + (long)m * lda + k0 + ch * 8);
        }
        #pragma unroll
        for (int i = 0; i < 8; i++) {              // B: 128 rows x 8 chunks = 1024
            int chunk = i * 128 + tid;
            int n = chunk >> 3, ch = chunk & 7;
            CP_ASYNC16(sB + n * 128 + ((ch ^ (n & 7)) << 4),
                       Borig + (long)n * Kel + k0 + ch * 8);
        }
    };

    issue(0); CP_COMMIT();
    issue(1); CP_COMMIT();

    for (int t = 0; t < T; t++) {
        CP_WAIT(1);
        __syncthreads();
        if (t + 2 < T) issue(t + 2);
        CP_COMMIT();
        const uint32_t stg = smbase + (t % STAGES) * STAGE_B;
        #pragma unroll
        for (int ks = 0; ks < 4; ks++) {
            const uint32_t sAo = ((((uint32_t)(ks << 1) + ghA) ^ m7a) << 4);
            const uint32_t sBo = ((((uint32_t)(ks << 1) + ghB) ^ n7b) << 4);
            uint32_t a[4][4], b[8][2];
            #pragma unroll
            for (int mi = 0; mi < 4; mi++)
                LDSM_X4(a[mi][0], a[mi][1], a[mi][2], a[mi][3],
                        stg + relA[mi] + sAo);
            #pragma unroll
            for (int nip = 0; nip < 4; nip++)
                LDSM_X4(b[2 * nip][0], b[2 * nip][1], b[2 * nip + 1][0], b[2 * nip + 1][1],
                        stg + relB[nip] + sBo);
            #pragma unroll
            for (int mi = 0; mi < 4; mi++)
                #pragma unroll
                for (int ni = 0; ni < 8; ni++)
                    MMA_F16(c[mi][ni], a[mi], b[ni]);
        }
    }

    // ---------------- epilogue: regs -> (+bias) -> GMEM ----------------
    const int bb = rowBase >> 9;                   // batch constant per CTA (S = 512)
    #pragma unroll
    for (int mi = 0; mi < 4; mi++) {
        int r0 = rowBase + wm + mi * 16 + gq;
        #pragma unroll
        for (int ni = 0; ni < 8; ni++) {
            int col = colBase + wn + ni * 8 + 2 * t4;
            float b0 = 0.0f, b1 = 0.0f;
            if (biasrow) {
                const float* bp = biasrow + ((long)gate * Bn + bb) * Hn + col;
                b0 = bp[0]; b1 = bp[1];
            }
            if (HALF_OUT) {
                __half* oplane = (__half*)outp + (long)gate * gateStride;
                *(__half2*)(oplane + (long)r0 * 512 + col) =
                    __floats2half2_rn(c[mi][ni][0] + b0, c[mi][ni][1] + b1);
                *(__half2*)(oplane + (long)(r0 + 8) * 512 + col) =
                    __floats2half2_rn(c[mi][ni][2] + b0, c[mi][ni][3] + b1);
            } else {
                float* oplane = (float*)outp + (long)gate * gateStride;
                *(float2*)(oplane + (long)r0 * 512 + col) =
                    make_float2(c[mi][ni][0] + b0, c[mi][ni][1] + b1);
                *(float2*)(oplane + (long)(r0 + 8) * 512 + col) =
                    make_float2(c[mi][ni][2] + b0, c[mi][ni][3] + b1);
            }
        }
    }
}

// ---------------- column mean over sequence (8-way s-split) ------------------------
__global__ void colmean_kernel(const float* __restrict__ in, float* __restrict__ out)
{
    const int sg = threadIdx.x >> 5, kl = threadIdx.x & 31;
    const int b = blockIdx.y, k = blockIdx.x * 32 + kl;
    __shared__ float red[8][32];
    const float* p = in + ((long)b * Sn + sg * 64) * Hn + k;
    float s = 0.0f;
    #pragma unroll 8
    for (int t = 0; t < 64; t++) s += p[(long)t * Hn];
    red[sg][kl] = s;
    __syncthreads();
    if (sg == 0) {
        float tot = 0.0f;
        #pragma unroll
        for (int i = 0; i < 8; i++) tot += red[i][kl];
        out[b * Hn + k] = tot * (1.0f / (float)Sn);
    }
}

// ---------------- small matmuls on dummy_h/combined (B=32 rows) --------------------
__global__ __launch_bounds__(512)
void smallmm_kernel(const float* __restrict__ dh, const float* __restrict__ comb,
                    const float* __restrict__ gW, const float* __restrict__ gb,
                    const float* __restrict__ Wd, const float* __restrict__ bvec,
                    float* __restrict__ gd, float* __restrict__ go,
                    float* __restrict__ dgf, float* __restrict__ biasrow)
{
    const int task = blockIdx.x, b = blockIdx.y, k = threadIdx.x;
    __shared__ float xs[512];
    __shared__ float ys[512];
    xs[k] = dh[b * Hn + k];
    if (task < 2) ys[k] = comb[b * Hn + k];
    __syncthreads();
    const int MM = Hn * Hn;
    if (task == 0) {
        const float* W1 = gW;          const float* W2 = gW + MM;
        float acc = gb[k];
        #pragma unroll 8
        for (int i = 0; i < Hn; i++) acc += xs[i] * W1[i * Hn + k] + ys[i] * W2[i * Hn + k];
        gd[b * Hn + k] = sigf(acc);
    } else if (task == 1) {
        const float* W1 = gW + 2 * MM; const float* W2 = gW + 3 * MM;
        float acc = gb[Hn + k];
        #pragma unroll 8
        for (int i = 0; i < Hn; i++) acc += xs[i] * W1[i * Hn + k] + ys[i] * W2[i * Hn + k];
        go[b * Hn + k] = sigf(acc);
    } else if (task == 2) {
        const float* W1 = gW + 4 * MM;
        float acc = gb[2 * Hn + k];
        #pragma unroll 8
        for (int i = 0; i < Hn; i++) acc += xs[i] * W1[i * Hn + k];
        dgf[b * Hn + k] = acc;
    } else {
        int g = task - 3;
        const float* W1 = Wd + (long)g * MM;
        float acc = bvec[g * Hn + k];
        #pragma unroll 8
        for (int i = 0; i < Hn; i++) acc += xs[i] * W1[i * Hn + k];
        biasrow[(g * Bn + b) * Hn + k] = acc;
    }
}

// ---------------- scores softmax over S+1 and dummy state update -------------------
__global__ void scorereduce_kernel(const float* __restrict__ gfz, const float* __restrict__ dgf,
                                   const float* __restrict__ gd, const float* __restrict__ go,
                                   const float* __restrict__ c, const float* __restrict__ dcold,
                                   float* __restrict__ dcnew, float* __restrict__ dhnew)
{
    const int sg = threadIdx.x >> 5, kl = threadIdx.x & 31;
    const int b = blockIdx.y, k = blockIdx.x * 32 + kl;
    const int id = b * Hn + k;
    __shared__ float rnum[8][32], rden[8][32];
    const float add = dgf[id];
    const float* gp = gfz + ((long)b * Sn + sg * 64) * Hn + k;
    const float* cp = c   + ((long)b * Sn + sg * 64) * Hn + k;
    float num = 0.0f, den = 0.0f;
    #pragma unroll 4
    for (int t = 0; t < 64; t++) {
        float e = expf(sigf(gp[(long)t * Hn] + add));
        num += e * cp[(long)t * Hn];
        den += e;
    }
    rnum[sg][kl] = num; rden[sg][kl] = den;
    __syncthreads();
    if (sg == 0) {
        float tn = 0.0f, td = 0.0f;
        #pragma unroll
        for (int i = 0; i < 8; i++) { tn += rnum[i][kl]; td += rden[i][kl]; }
        float eg = expf(gd[id]);
        tn += eg * dcold[id];
        td += eg;
        float dcn = tn / td;
        dcnew[id] = dcn;
        dhnew[id] = go[id] * tanhf(dcn);
    }
}

// ---------------- build Xbig slots [0:2048) = [h | hb | ha | sw_h] (fp16) ----------
__global__ void buildxcat_kernel(const float* __restrict__ h, const int* __restrict__ pos,
                                 __half* __restrict__ X)
{
    long id = (long)blockIdx.x * blockDim.x + threadIdx.x;
    if (id >= (long)Nn * Hn) return;
    int n = (int)(id >> 9), k = (int)(id & 511);
    int b = n >> 9, s = n & 511;
    long hb_base = (long)n * Hn + k;
    float hv = h[hb_base];
    float hb = (s >= 1 ? h[hb_base - Hn] : 0.0f) + (s >= 2 ? h[hb_base - 2 * Hn] : 0.0f);
    float ha = (s <= Sn - 2 ? h[hb_base + Hn] : 0.0f) + (s <= Sn - 3 ? h[hb_base + 2 * Hn] : 0.0f);
    int p = pos[n];
    float sw = (p > 0) ? h[((long)((b << 9) + p - 1)) * Hn + k] : 0.0f;
    long xo = (long)n * KBIG + k;
    X[xo]         = __float2half_rn(hv);
    X[xo + 512]   = __float2half_rn(hb);
    X[xo + 1024]  = __float2half_rn(ha);
    X[xo + 1536]  = __float2half_rn(sw);
}

// ---------------- emb slot of Xbig (once) ------------------------------------------
__global__ void copyemb_kernel(const float* __restrict__ w, __half* __restrict__ X)
{
    long id = (long)blockIdx.x * blockDim.x + threadIdx.x;
    if (id >= (long)Nn * WDn) return;
    int n = (int)(id >> 9), k = (int)(id & 511);
    X[(long)n * KBIG + 2048 + k] = __float2half_rn(w[id]);
}

// ---------------- Wbig[c][k] (K-major fp16) + gWT ----------------------------------
__global__ void buildw_kernel(const float* __restrict__ Wx, const float* __restrict__ Wh,
                              const float* __restrict__ Ws, const float* __restrict__ Wi,
                              __half* __restrict__ W)
{
    long id = (long)blockIdx.x * blockDim.x + threadIdx.x;
    if (id >= (long)NTOT * KBIG) return;
    int k = (int)(id % KBIG);
    int c = (int)(id / KBIG);
    int g = c >> 9, hcol = c & 511;
    float v;
    if (k < 512)        v = Wx[((long)g * 512  + k)          * Hn + hcol];
    else if (k < 1536)  v = Wh[((long)g * 1024 + (k - 512))  * Hn + hcol];
    else if (k < 2048)  v = Ws[((long)g * 512  + (k - 1536)) * Hn + hcol];
    else                v = Wi[((long)g * 512  + (k - 2048)) * Hn + hcol];
    W[id] = __float2half_rn(v);
}
__global__ void buildgwt_kernel(const float* __restrict__ gW, __half* __restrict__ WT)
{
    int id = blockIdx.x * blockDim.x + threadIdx.x;
    if (id >= Hn * Hn) return;
    int c = id >> 9, k = id & 511;
    WT[id] = __float2half_rn(gW[5 * Hn * Hn + k * Hn + c]);
}

// ---------------- gate combine (half2 Z, 2 elems/thread) ---------------------------
__global__ void combine_kernel(const __half2* __restrict__ Z2, const float* __restrict__ c_in,
                               const int* __restrict__ pos, const float* __restrict__ dcold,
                               float* __restrict__ h_out, float* __restrict__ c_out)
{
    long id = (long)blockIdx.x * blockDim.x + threadIdx.x;   // over Nn*256 pairs
    if (id >= (long)Nn * 256) return;
    int n = (int)(id >> 8), kp = (int)(id & 255);
    int k = kp * 2;
    int b = n >> 9, s = n & 511;
    const long gs2 = (long)Nn * 256;

    float2 z[8];
    #pragma unroll
    for (int g = 0; g < 8; g++) z[g] = __half22float2(Z2[(long)g * gs2 + id]);

    long base = (long)n * Hn + k;
    float2 cf = *(const float2*)(c_in + base);
    float2 cb = make_float2(0.f, 0.f), ca = make_float2(0.f, 0.f);
    if (s >= 1) { float2 v = *(const float2*)(c_in + base - Hn);     cb.x += v.x; cb.y += v.y; }
    if (s >= 2) { float2 v = *(const float2*)(c_in + base - 2 * Hn); cb.x += v.x; cb.y += v.y; }
    if (s <= Sn - 2) { float2 v = *(const float2*)(c_in + base + Hn);     ca.x += v.x; ca.y += v.y; }
    if (s <= Sn - 3) { float2 v = *(const float2*)(c_in + base + 2 * Hn); ca.x += v.x; ca.y += v.y; }
    int p = pos[n];
    float2 swc = make_float2(0.f, 0.f);
    if (p > 0) swc = *(const float2*)(c_in + ((long)((b << 9) + p - 1)) * Hn + k);
    float2 tdc = *(const float2*)(dcold + (b << 9) + k);

    float2 cn_o, hn_o;
    {   // elem 0
        float es[6], sum = 0.0f;
        float zz[8] = {z[0].x, z[1].x, z[2].x, z[3].x, z[4].x, z[5].x, z[6].x, z[7].x};
        #pragma unroll
        for (int i = 0; i < 6; i++) { es[i] = expf(sigf(zz[i])); sum += es[i]; }
        float inv = 1.0f / sum;
        float u = tanhf(zz[7]), o = sigf(zz[6]);
        float cn = (es[0] * cb.x + es[1] * ca.x + es[2] * cf.x + es[3] * tdc.x
                    + es[4] * swc.x + es[5] * u) * inv;
        cn_o.x = cn; hn_o.x = o * tanhf(cn);
    }
    {   // elem 1
        float es[6], sum = 0.0f;
        float zz[8] = {z[0].y, z[1].y, z[2].y, z[3].y, z[4].y, z[5].y, z[6].y, z[7].y};
        #pragma unroll
        for (int i = 0; i < 6; i++) { es[i] = expf(sigf(zz[i])); sum += es[i]; }
        float inv = 1.0f / sum;
        float u = tanhf(zz[7]), o = sigf(zz[6]);
        float cn = (es[0] * cb.y + es[1] * ca.y + es[2] * cf.y + es[3] * tdc.y
                    + es[4] * swc.y + es[5] * u) * inv;
        cn_o.y = cn; hn_o.y = o * tanhf(cn);
    }
    *(float2*)(c_out + base) = cn_o;
    *(float2*)(h_out + base) = hn_o;
}

// =====================================================================================
extern "C" void kernel_launch(void* const* d_in, const int* in_sizes, int n_in,
                              void* d_out, int out_size)
{
    const float* word_inputs = (const float*)d_in[0];
    const float* init_h      = (const float*)d_in[1];
    const float* init_c      = (const float*)d_in[2];
    const float* Wx          = (const float*)d_in[3];
    const float* Wh          = (const float*)d_in[4];
    const float* Wi          = (const float*)d_in[5];
    const float* Wd          = (const float*)d_in[6];
    const float* Ws          = (const float*)d_in[7];
    const float* bvec        = (const float*)d_in[8];
    const float* gW          = (const float*)d_in[9];
    const float* gb          = (const float*)d_in[10];
    const int*   postab      = (const int*)d_in[11];
    float* out = (float*)d_out;

    float *hA, *hB, *cA, *cB, *gfz;
    float *dh, *dc, *comb, *gd, *go, *dgf, *biasrow;
    __half *Zb, *Xbig, *Wbig, *gWT;
    cudaGetSymbolAddress((void**)&Zb,      g_Z);
    cudaGetSymbolAddress((void**)&Xbig,    g_Xbig);
    cudaGetSymbolAddress((void**)&Wbig,    g_Wbig);
    cudaGetSymbolAddress((void**)&gWT,     g_gWT);
    cudaGetSymbolAddress((void**)&hA,      g_hA);
    cudaGetSymbolAddress((void**)&hB,      g_hB);
    cudaGetSymbolAddress((void**)&cA,      g_cA);
    cudaGetSymbolAddress((void**)&cB,      g_cB);
    cudaGetSymbolAddress((void**)&gfz,     g_gfz);
    cudaGetSymbolAddress((void**)&dh,      g_dh);
    cudaGetSymbolAddress((void**)&dc,      g_dc);
    cudaGetSymbolAddress((void**)&comb,    g_comb);
    cudaGetSymbolAddress((void**)&gd,      g_gd);
    cudaGetSymbolAddress((void**)&go,      g_go);
    cudaGetSymbolAddress((void**)&dgf,     g_dgf);
    cudaGetSymbolAddress((void**)&biasrow, g_biasrow);

    cudaFuncSetAttribute(mmagemm<true>,  cudaFuncAttributeMaxDynamicSharedMemorySize, GEMM_SMEM);
    cudaFuncSetAttribute(mmagemm<false>, cudaFuncAttributeMaxDynamicSharedMemorySize, GEMM_SMEM);

    const long stateBytes = (long)Nn * Hn * sizeof(float);

    // ---- init ----
    cudaMemcpyAsync(hA, init_h, stateBytes, cudaMemcpyDeviceToDevice);
    cudaMemcpyAsync(cA, init_c, stateBytes, cudaMemcpyDeviceToDevice);
    colmean_kernel<<<dim3(Hn / 32, Bn), 256>>>(init_h, dh + 0);
    colmean_kernel<<<dim3(Hn / 32, Bn), 256>>>(init_c, dc + 0);
    buildw_kernel<<<(int)(((long)NTOT * KBIG + 255) / 256), 256>>>(Wx, Wh, Ws, Wi, Wbig);
    buildgwt_kernel<<<(Hn * Hn) / 256, 256>>>(gW, gWT);
    copyemb_kernel<<<(int)(((long)Nn * WDn) / 256), 256>>>(word_inputs, Xbig);

    for (int L = 0; L < NUM_LAYERS; L++) {
        const float* h_in = (L & 1) ? hB : hA;
        const float* c_in = (L & 1) ? cB : cA;
        float* h_out = (L == NUM_LAYERS - 1) ? out : ((L & 1) ? hA : hB);
        float* c_out = (L & 1) ? cA : cB;
        float* dh_in  = dh + (L & 1) * (Bn * Hn);
        float* dh_out = dh + (1 - (L & 1)) * (Bn * Hn);
        float* dc_in  = dc + (L & 1) * (Bn * Hn);
        float* dc_out = dc + (1 - (L & 1)) * (Bn * Hn);

        colmean_kernel<<<dim3(Hn / 32, Bn), 256>>>(h_in, comb);
        smallmm_kernel<<<dim3(11, Bn), 512>>>(dh_in, comb, gW, gb, Wd, bvec,
                                              gd, go, dgf, biasrow);
        // Xbig = [h | hb | ha | sw_h] fp16 (emb slot persistent)
        buildxcat_kernel<<<(int)(((long)Nn * Hn) / 256), 256>>>(h_in, postab, Xbig);
        // gfz = h @ gWhf  (A = Xbig slot 0, lda = KBIG; fp32 out)
        mmagemm<false><<<dim3(4, Nn / 128, 1), 128, GEMM_SMEM>>>(Xbig, KBIG, gWT, Hn,
                                                                 gfz, 0, nullptr);
        scorereduce_kernel<<<dim3(Hn / 32, Bn), 256>>>(gfz, dgf, gd, go, c_in,
                                                       dc_in, dc_out, dh_out);
        // Z[g] = Xbig @ Wbig[g] + biasrow[g]  (fp16 out)
        mmagemm<true><<<dim3(4, Nn / 128, NGn), 128, GEMM_SMEM>>>(Xbig, KBIG, Wbig, KBIG,
                                                                  Zb, GS2 * 2, biasrow);
        combine_kernel<<<(int)(((long)Nn * 256) / 256), 256>>>((const __half2*)Zb, c_in,
                                                               postab, dc_in, h_out, c_out);
    }
}